// round 12
// baseline (speedup 1.0000x reference)
#include <cuda_runtime.h>
#include <cstdint>

#define DIMX 1024
#define NEXP 8
#define HIDX 4096
#define TTOK 4096   // B*S = 2*2048

// ---------------- static scratch (no allocations allowed) ----------------
__device__ signed char g_wq1[(size_t)NEXP * HIDX * DIMX];   // ternary w1
__device__ signed char g_wq2[(size_t)NEXP * DIMX * HIDX];   // ternary w2
__device__ signed char g_wqr[NEXP * DIMX];
__device__ signed char g_wqn[NEXP * DIMX];
__device__ float g_partial[18 * 128];
__device__ float g_mval[18];
__device__ signed char g_xq[(size_t)TTOK * DIMX];
__device__ float g_deqx[TTOK];
__device__ int   g_cnt[NEXP];
__device__ int   g_tok[NEXP * TTOK];
__device__ int   g_tpe[TTOK * 2];    // (expert<<16)|pos per token slot
__device__ float g_tg[TTOK * 2];     // gates per token slot
__device__ int   g_hcnt[NEXP * 32];  // per-(expert,mtile) completion counters
__device__ float g_h[(size_t)2 * TTOK * HIDX];               // fp32 hidden
__device__ signed char g_hq[(size_t)2 * TTOK * HIDX];        // int8 hidden
__device__ float g_deqh[2 * TTOK];
__device__ int g_yp0[(size_t)2 * TTOK * DIMX];               // int32 partial (K half 0)
__device__ int g_yp1[(size_t)2 * TTOK * DIMX];               // int32 partial (K half 1)

// ---------------- helpers ----------------
__device__ __forceinline__ signed char terq(float x) {
    float r = rintf(x);
    r = fminf(1.f, fmaxf(-1.f, r));
    return (signed char)(int)r;
}
__device__ __forceinline__ signed char qi8(float x) {
    float r = rintf(x);
    r = fminf(127.f, fmaxf(-128.f, r));
    return (signed char)(int)r;
}
__device__ __forceinline__ uint32_t s2u(const void* p) {
    uint32_t a;
    asm("{ .reg .u64 t; cvta.to.shared.u64 t, %1; cvt.u32.u64 %0, t; }" : "=r"(a) : "l"(p));
    return a;
}
__device__ __forceinline__ void ldsm4(unsigned& r0, unsigned& r1, unsigned& r2, unsigned& r3,
                                      uint32_t a) {
    asm volatile("ldmatrix.sync.aligned.m8n8.x4.shared.b16 {%0,%1,%2,%3}, [%4];"
                 : "=r"(r0), "=r"(r1), "=r"(r2), "=r"(r3) : "r"(a));
}

// w2 ternarize slice: block `bid` covers float4 range [bid*1024, bid*1024+1024)
__device__ __forceinline__ void w2_slice(const float4* __restrict__ w2v, int bid, int tid) {
    size_t base = (size_t)bid * 1024;
    #pragma unroll
    for (int j = 0; j < 4; j++) {
        size_t i = base + tid + j * 256;
        int e = (int)(i >> 20);                 // 1048576 float4 per expert
        float sc = 1.0f / g_mval[10 + e];
        float4 v = w2v[i];
        char4 c;
        c.x = terq(v.x * sc); c.y = terq(v.y * sc);
        c.z = terq(v.z * sc); c.w = terq(v.w * sc);
        ((char4*)g_wq2)[i] = c;
    }
}

// ---------------- 1) weight stats: per-tensor sum |w| ----------------
__global__ void stats_partial(const float* __restrict__ wr, const float* __restrict__ wn,
                              const float* __restrict__ w1, const float* __restrict__ w2) {
    int slot = blockIdx.y, chunk = blockIdx.x;
    const float4* p;
    int nvec;
    if (slot < 2) {
        if (chunk != 0) return;
        p = (const float4*)(slot ? wn : wr);
        nvec = NEXP * DIMX / 4;
    } else if (slot < 10) {
        p = (const float4*)(w1 + (size_t)(slot - 2) * HIDX * DIMX) + (size_t)chunk * 8192;
        nvec = 8192;
    } else {
        p = (const float4*)(w2 + (size_t)(slot - 10) * DIMX * HIDX) + (size_t)chunk * 8192;
        nvec = 8192;
    }
    float s = 0.f;
    for (int i = threadIdx.x; i < nvec; i += 256) {
        float4 v = p[i];
        s += fabsf(v.x) + fabsf(v.y) + fabsf(v.z) + fabsf(v.w);
    }
    __shared__ float sh[8];
    #pragma unroll
    for (int o = 16; o; o >>= 1) s += __shfl_xor_sync(0xffffffffu, s, o);
    if ((threadIdx.x & 31) == 0) sh[threadIdx.x >> 5] = s;
    __syncthreads();
    if (threadIdx.x == 0) {
        float t = 0.f;
        #pragma unroll
        for (int j = 0; j < 8; j++) t += sh[j];
        g_partial[slot * 128 + chunk] = t;
    }
}

// ---------------- 2) finalize: mvals + small-weight ternarize + zero counters ----------------
__global__ void finalize(const float* __restrict__ wr, const float* __restrict__ wn) {
    int tid = threadIdx.x;
    __shared__ float sm[18];
    if (tid < 18) {
        int nc = (tid < 2) ? 1 : 128;
        float sum = 0.f;
        for (int c = 0; c < nc; c++) sum += g_partial[tid * 128 + c];
        float nelem = (tid < 2) ? (float)(NEXP * DIMX) : (float)((size_t)HIDX * DIMX);
        float m = fmaxf(sum / nelem, 1e-5f);
        g_mval[tid] = m;
        sm[tid] = m;
    }
    if (tid < NEXP) g_cnt[tid] = 0;
    g_hcnt[tid] = 0;   // 256 counters, one per thread
    __syncthreads();
    float sc0 = 1.0f / sm[0], sc1 = 1.0f / sm[1];
    for (int i = tid; i < NEXP * DIMX; i += 256) {
        g_wqr[i] = terq(wr[i] * sc0);
        g_wqn[i] = terq(wn[i] * sc1);
    }
}

// ---------------- 3) mega: w1 ternarize (z=0) + act-quant+router (z=1) ----------------
__global__ __launch_bounds__(256) void mega(const float* __restrict__ w1,
                                            const float* __restrict__ x,
                                            const float* __restrict__ eps) {
    int z = blockIdx.z;
    int tid = threadIdx.x;
    if (z == 0) {
        size_t i = (size_t)blockIdx.x * 256 + tid;   // float4 index, exactly covers w1
        int e = (int)(i >> 20);
        float sc = 1.0f / g_mval[2 + e];
        float4 v = ((const float4*)w1)[i];
        char4 c;
        c.x = terq(v.x * sc); c.y = terq(v.y * sc); c.z = terq(v.z * sc); c.w = terq(v.w * sc);
        ((char4*)g_wq1)[i] = c;
        return;
    }
    int t = blockIdx.x;
    if (t >= TTOK) return;

    __shared__ float shs[8], shm[8], svals[8], sdq[1];
    __shared__ int sx[256];

    float4 v = ((const float4*)(x + (size_t)t * DIMX))[tid];
    float ss = v.x * v.x + v.y * v.y + v.z * v.z + v.w * v.w;
    float am = fmaxf(fmaxf(fabsf(v.x), fabsf(v.y)), fmaxf(fabsf(v.z), fabsf(v.w)));
    #pragma unroll
    for (int o = 16; o; o >>= 1) {
        ss += __shfl_xor_sync(0xffffffffu, ss, o);
        am = fmaxf(am, __shfl_xor_sync(0xffffffffu, am, o));
    }
    if ((tid & 31) == 0) { shs[tid >> 5] = ss; shm[tid >> 5] = am; }
    __syncthreads();
    float tss = 0.f, tam = 0.f;
    #pragma unroll
    for (int j = 0; j < 8; j++) { tss += shs[j]; tam = fmaxf(tam, shm[j]); }
    float rs = rsqrtf(tss / (float)DIMX + 1e-6f);
    float a = fmaxf(tam * rs, 1e-5f);
    float sc = 127.0f / a;
    if (tid == 0) { g_deqx[t] = a / 127.0f; sdq[0] = a / 127.0f; }
    char4 c;
    c.x = qi8(v.x * rs * sc); c.y = qi8(v.y * rs * sc);
    c.z = qi8(v.z * rs * sc); c.w = qi8(v.w * rs * sc);
    ((char4*)(g_xq + (size_t)t * DIMX))[tid] = c;
    int ci;
    memcpy(&ci, &c, 4);
    sx[tid] = ci;
    __syncthreads();

    // router: warp w handles expert w
    int w = tid >> 5, lane = tid & 31;
    const int* wrp = (const int*)(g_wqr + w * DIMX);
    const int* wnp = (const int*)(g_wqn + w * DIMX);
    int ar = 0, an = 0;
    #pragma unroll
    for (int j = 0; j < 8; j++) {
        int xi = sx[lane + 32 * j];
        ar = __dp4a(xi, wrp[lane + 32 * j], ar);
        an = __dp4a(xi, wnp[lane + 32 * j], an);
    }
    #pragma unroll
    for (int o = 16; o; o >>= 1) {
        ar += __shfl_xor_sync(0xffffffffu, ar, o);
        an += __shfl_xor_sync(0xffffffffu, an, o);
    }
    if (lane == 0) {
        float dq = sdq[0];
        float lg = (float)ar * dq * g_mval[0];
        float nl = (float)an * dq * g_mval[1];
        float sp = fmaxf(nl, 0.f) + log1pf(expf(-fabsf(nl)));
        svals[w] = lg + eps[t * NEXP + w] * sp;
    }
    __syncthreads();
    if (tid == 0) {
        float v0 = -1e30f, v1 = -1e30f;
        int i0 = 0, i1 = 0;
        #pragma unroll
        for (int e = 0; e < NEXP; e++) {
            float vv = svals[e];
            if (vv > v0) { v1 = v0; i1 = i0; v0 = vv; i0 = e; }
            else if (vv > v1) { v1 = vv; i1 = e; }
        }
        float ex = expf(v1 - v0);
        float inv = 1.0f / (1.0f + ex);
        int p0 = atomicAdd(&g_cnt[i0], 1);
        g_tok[i0 * TTOK + p0] = t;
        int p1 = atomicAdd(&g_cnt[i1], 1);
        g_tok[i1 * TTOK + p1] = t;
        g_tpe[t * 2]     = (i0 << 16) | p0;
        g_tpe[t * 2 + 1] = (i1 << 16) | p1;
        g_tg[t * 2]      = inv;
        g_tg[t * 2 + 1]  = ex * inv;
    }
}

// ---------------- 4/5) pipelined int8 tensor-core grouped GEMM ----------------
// Tile 128x128, BKK=64, 3-stage cp.async pipeline, 3 blocks/SM.
// MODE 1 additionally: (a) ternarizes a w2 slice per block (hides DRAM work
// under tensor work), (b) the LAST n-block of each (expert,mtile) performs the
// hidden-state rmsnorm+int8 quant for its 128 rows (hides h_quant the same way).
// MODE 2 uses a deterministic K-split into int32 partial buffers.
#define BM 128
#define BN 128
#define BKK 64
#define LDSS 80          // 64 + 16 pad: conflict-free ldmatrix phases
#define STG_STRIDE (2 * BM * LDSS)   // A stage + B stage = 20480
#define GSMEM (3 * STG_STRIDE)       // 3 stages = 61440 B

__device__ __forceinline__ void mma8(int (&c)[4], const unsigned (&a)[4], const unsigned (&b)[2]) {
    asm volatile(
        "mma.sync.aligned.m16n8k32.row.col.s32.s8.s8.s32 "
        "{%0,%1,%2,%3}, {%4,%5,%6,%7}, {%8,%9}, {%0,%1,%2,%3};\n"
        : "+r"(c[0]), "+r"(c[1]), "+r"(c[2]), "+r"(c[3])
        : "r"(a[0]), "r"(a[1]), "r"(a[2]), "r"(a[3]), "r"(b[0]), "r"(b[1]));
}

template <int MODE>
__global__ __launch_bounds__(256, 3) void bit_gemm(const float* __restrict__ w2fp) {
    constexpr int K = (MODE == 1) ? DIMX : HIDX;          // full row stride
    constexpr int KRUN = (MODE == 1) ? DIMX : HIDX / 2;   // K covered per block
    constexpr int N = (MODE == 1) ? HIDX : DIMX;
    constexpr int NITER = KRUN / BKK;
    const int e = (MODE == 1) ? blockIdx.z : (blockIdx.z & 7);
    const int ksp = (MODE == 1) ? 0 : (blockIdx.z >> 3);
    const int kbase = ksp * KRUN;
    const int cnt = g_cnt[e];
    const int m0 = blockIdx.y * BM;
    const int tid = threadIdx.x;
    if (m0 >= cnt) {
        if (MODE == 1) {
            int bid = blockIdx.x + (int)gridDim.x * (blockIdx.y + (int)gridDim.y * blockIdx.z);
            w2_slice((const float4*)w2fp, bid, tid);
        }
        return;
    }
    const int n0 = blockIdx.x * BN;
    int off = 0;
    #pragma unroll
    for (int j = 0; j < NEXP; j++) if (j < e) off += g_cnt[j];

    extern __shared__ char dsm[];
    const uint32_t smb = s2u(dsm);

    const int lane = tid & 31, warp = tid >> 5;
    const int wm = warp >> 2, wn = warp & 3;   // 2x4 warp grid, warp tile 64x32

    int acc[4][4][4];
    #pragma unroll
    for (int a = 0; a < 4; a++)
        #pragma unroll
        for (int b = 0; b < 4; b++)
            #pragma unroll
            for (int c = 0; c < 4; c++) acc[a][b][c] = 0;

    const int lr = tid >> 1;            // staged row (0..127)
    const int lcb = (tid & 1) * 32;     // byte offset within 64B k-chunk
    const bool aok = (m0 + lr) < cnt;
    const signed char* Ap;
    if (MODE == 1) {
        int tok = aok ? g_tok[e * TTOK + m0 + lr] : 0;
        Ap = g_xq + (size_t)tok * K + kbase + lcb;
    } else {
        int r = aok ? (off + m0 + lr) : 0;
        Ap = g_hq + (size_t)r * K + kbase + lcb;
    }
    const unsigned aSz = aok ? 16u : 0u;
    const signed char* wsrc = (MODE == 1) ? g_wq1 : g_wq2;
    const signed char* Bp = wsrc + (size_t)e * N * K + (size_t)(n0 + lr) * K + kbase + lcb;

    const uint32_t cpOff = (uint32_t)(lr * LDSS + lcb);
    // ldmatrix lane offsets
    const uint32_t aLO = (uint32_t)((lane & 15) * LDSS + (lane >> 4) * 16);
    const uint32_t bLO = (uint32_t)(((lane >> 4) * 8 + (lane & 7)) * LDSS + ((lane >> 3) & 1) * 16);

    auto prefetch = [&](int it) {
        int s = it;
        while (s >= 3) s -= 3;
        uint32_t ab = smb + s * STG_STRIDE + cpOff;
        uint32_t bb = ab + BM * LDSS;
        const signed char* as = Ap;
        const signed char* bs = Bp;
        unsigned asz = 0, bsz = 0;
        if (it < NITER) {
            as = Ap + it * BKK;
            bs = Bp + it * BKK;
            asz = aSz;
            bsz = 16;
        }
        asm volatile("cp.async.cg.shared.global [%0], [%1], 16, %2;"
                     :: "r"(ab), "l"(as), "r"(asz) : "memory");
        asm volatile("cp.async.cg.shared.global [%0], [%1], 16, %2;"
                     :: "r"(ab + 16), "l"(as + 16), "r"(asz) : "memory");
        asm volatile("cp.async.cg.shared.global [%0], [%1], 16, %2;"
                     :: "r"(bb), "l"(bs), "r"(bsz) : "memory");
        asm volatile("cp.async.cg.shared.global [%0], [%1], 16, %2;"
                     :: "r"(bb + 16), "l"(bs + 16), "r"(bsz) : "memory");
        asm volatile("cp.async.commit_group;" ::: "memory");
    };

    prefetch(0);
    prefetch(1);
    #pragma unroll 1
    for (int i = 0; i < NITER; i++) {
        // stage (i+2)%3 == (i-1)%3 was released by the trailing barrier of iter i-1
        prefetch(i + 2);
        asm volatile("cp.async.wait_group 2;" ::: "memory");   // my group-i copies landed
        __syncthreads();                                       // everyone's group-i copies landed
        int s = i;
        while (s >= 3) s -= 3;
        const uint32_t aB = smb + s * STG_STRIDE;
        const uint32_t bB = aB + BM * LDSS;
        #pragma unroll
        for (int ks = 0; ks < 2; ks++) {
            unsigned af[4][4];
            #pragma unroll
            for (int mi = 0; mi < 4; mi++)
                ldsm4(af[mi][0], af[mi][1], af[mi][2], af[mi][3],
                      aB + (uint32_t)((wm * 64 + mi * 16) * LDSS + ks * 32) + aLO);
            unsigned bf[4][2];
            #pragma unroll
            for (int np = 0; np < 2; np++)
                ldsm4(bf[np * 2][0], bf[np * 2][1], bf[np * 2 + 1][0], bf[np * 2 + 1][1],
                      bB + (uint32_t)((wn * 32 + np * 16) * LDSS + ks * 32) + bLO);
            #pragma unroll
            for (int mi = 0; mi < 4; mi++)
                #pragma unroll
                for (int ni = 0; ni < 4; ni++) mma8(acc[mi][ni], af[mi], bf[ni]);
        }
        __syncthreads();                                       // release stage i for reuse
    }

    if (MODE == 1) {
        const float m1 = g_mval[2 + e];
        #pragma unroll
        for (int mi = 0; mi < 4; mi++) {
            #pragma unroll
            for (int half = 0; half < 2; half++) {
                int rrow = wm * 64 + mi * 16 + (lane >> 2) + half * 8;
                int pos = m0 + rrow;
                if (pos < cnt) {
                    float d = g_deqx[g_tok[e * TTOK + pos]] * m1;
                    float* hrow = g_h + (size_t)(off + pos) * HIDX + n0;
                    #pragma unroll
                    for (int ni = 0; ni < 4; ni++) {
                        int col = wn * 32 + ni * 8 + (lane & 3) * 2;
                        float2 v;
                        v.x = fmaxf(0.f, (float)acc[mi][ni][half * 2 + 0] * d);
                        v.y = fmaxf(0.f, (float)acc[mi][ni][half * 2 + 1] * d);
                        *(float2*)(hrow + col) = v;
                    }
                }
            }
        }
        // publish h slice, then count arrivals for this (expert, mtile)
        __threadfence();
        __syncthreads();
        __shared__ int sfin;
        if (tid == 0)
            sfin = (atomicAdd(&g_hcnt[e * 32 + blockIdx.y], 1) == 31);
        __syncthreads();
        if (sfin) {
            __threadfence();   // acquire: other blocks' h writes now visible
            int nrows = min(BM, cnt - m0);
            for (int r = warp; r < nrows; r += 8) {
                size_t row = (size_t)(off + m0 + r);
                const float4* hp = (const float4*)(g_h + row * HIDX);
                float ss = 0.f, am = 0.f;
                #pragma unroll 4
                for (int j = lane; j < HIDX / 4; j += 32) {
                    float4 v = hp[j];
                    ss += v.x * v.x + v.y * v.y + v.z * v.z + v.w * v.w;
                    am = fmaxf(am, fmaxf(fmaxf(fabsf(v.x), fabsf(v.y)),
                                         fmaxf(fabsf(v.z), fabsf(v.w))));
                }
                #pragma unroll
                for (int o = 16; o; o >>= 1) {
                    ss += __shfl_xor_sync(0xffffffffu, ss, o);
                    am = fmaxf(am, __shfl_xor_sync(0xffffffffu, am, o));
                }
                float rs2 = rsqrtf(ss / (float)HIDX + 1e-6f);
                float a = fmaxf(am * rs2, 1e-5f);
                float sc = 127.0f / a;
                if (lane == 0) g_deqh[row] = a / 127.0f;
                char4* dst = (char4*)(g_hq + row * HIDX);
                #pragma unroll 4
                for (int j = lane; j < HIDX / 4; j += 32) {
                    float4 v = hp[j];
                    char4 c;
                    c.x = qi8(v.x * rs2 * sc); c.y = qi8(v.y * rs2 * sc);
                    c.z = qi8(v.z * rs2 * sc); c.w = qi8(v.w * rs2 * sc);
                    dst[j] = c;
                }
            }
        }
        // this block's w2 ternarize slice (overlaps with other blocks' MMA work)
        int bid = blockIdx.x + (int)gridDim.x * (blockIdx.y + (int)gridDim.y * blockIdx.z);
        w2_slice((const float4*)w2fp, bid, tid);
    } else {
        int* yp = ksp ? g_yp1 : g_yp0;
        #pragma unroll
        for (int mi = 0; mi < 4; mi++) {
            #pragma unroll
            for (int half = 0; half < 2; half++) {
                int rrow = wm * 64 + mi * 16 + (lane >> 2) + half * 8;
                int pos = m0 + rrow;
                if (pos < cnt) {
                    int* yrow = yp + (size_t)(off + pos) * DIMX + n0;
                    #pragma unroll
                    for (int ni = 0; ni < 4; ni++) {
                        int col = wn * 32 + ni * 8 + (lane & 3) * 2;
                        int2 v;
                        v.x = acc[mi][ni][half * 2 + 0];
                        v.y = acc[mi][ni][half * 2 + 1];
                        *(int2*)(yrow + col) = v;
                    }
                }
            }
        }
    }
}

// ---------------- 6) gated combine (deterministic, atomic-free) ----------------
__global__ void combine(float* __restrict__ out) {
    __shared__ int soff[NEXP];
    int t = blockIdx.x, i = threadIdx.x;
    if (i == 0) {
        int o = 0;
        #pragma unroll
        for (int j = 0; j < NEXP; j++) { soff[j] = o; o += g_cnt[j]; }
    }
    __syncthreads();
    int a0 = g_tpe[t * 2], a1 = g_tpe[t * 2 + 1];
    int e0 = a0 >> 16, e1 = a1 >> 16;
    int row0 = soff[e0] + (a0 & 0xFFFF);
    int row1 = soff[e1] + (a1 & 0xFFFF);
    float d0 = g_deqh[row0] * g_mval[10 + e0] * g_tg[t * 2];
    float d1 = g_deqh[row1] * g_mval[10 + e1] * g_tg[t * 2 + 1];
    size_t r0 = (size_t)row0 * DIMX;
    size_t r1 = (size_t)row1 * DIMX;
    int4 p00 = ((const int4*)(g_yp0 + r0))[i];
    int4 p01 = ((const int4*)(g_yp1 + r0))[i];
    int4 p10 = ((const int4*)(g_yp0 + r1))[i];
    int4 p11 = ((const int4*)(g_yp1 + r1))[i];
    float4 o;
    o.x = (float)(p00.x + p01.x) * d0 + (float)(p10.x + p11.x) * d1;
    o.y = (float)(p00.y + p01.y) * d0 + (float)(p10.y + p11.y) * d1;
    o.z = (float)(p00.z + p01.z) * d0 + (float)(p10.z + p11.z) * d1;
    o.w = (float)(p00.w + p01.w) * d0 + (float)(p10.w + p11.w) * d1;
    ((float4*)(out + (size_t)t * DIMX))[i] = o;
}

// ---------------- launch ----------------
extern "C" void kernel_launch(void* const* d_in, const int* in_sizes, int n_in,
                              void* d_out, int out_size) {
    const float* x   = (const float*)d_in[0];
    const float* eps = (const float*)d_in[1];
    const float* wr  = (const float*)d_in[2];
    const float* wn  = (const float*)d_in[3];
    const float* w1  = (const float*)d_in[4];
    const float* w2  = (const float*)d_in[5];
    float* out = (float*)d_out;

    cudaFuncSetAttribute(bit_gemm<1>, cudaFuncAttributeMaxDynamicSharedMemorySize, GSMEM);
    cudaFuncSetAttribute(bit_gemm<2>, cudaFuncAttributeMaxDynamicSharedMemorySize, GSMEM);

    stats_partial<<<dim3(128, 18), 256>>>(wr, wn, w1, w2);      // 1
    finalize<<<1, 256>>>(wr, wn);                               // 2
    mega<<<dim3(32768, 1, 2), 256>>>(w1, x, eps);               // 3
    bit_gemm<1><<<dim3(HIDX / BN, TTOK / BM, NEXP), 256, GSMEM>>>(w2);   // 4 <- profiled (h-quant fused)
    bit_gemm<2><<<dim3(DIMX / BN, TTOK / BM, NEXP * 2), 256, GSMEM>>>(nullptr);  // 5 (K-split)
    combine<<<TTOK, 256>>>(out);                                // 6
}

// round 13
// speedup vs baseline: 1.0745x; 1.0745x over previous
#include <cuda_runtime.h>
#include <cstdint>

#define DIMX 1024
#define NEXP 8
#define HIDX 4096
#define TTOK 4096   // B*S = 2*2048
#define NPERS 444   // 148 SMs x 3 blocks

// ---------------- static scratch (no allocations allowed) ----------------
__device__ signed char g_wq1[(size_t)NEXP * HIDX * DIMX];   // ternary w1
__device__ signed char g_wq2[(size_t)NEXP * DIMX * HIDX];   // ternary w2
__device__ signed char g_wqr[NEXP * DIMX];
__device__ signed char g_wqn[NEXP * DIMX];
__device__ float g_partial[18 * 128];
__device__ float g_mval[18];
__device__ signed char g_xq[(size_t)TTOK * DIMX];
__device__ float g_deqx[TTOK];
__device__ int   g_cnt[NEXP];
__device__ int   g_work[2];          // work-steal counters (gemm1, gemm2)
__device__ int   g_tok[NEXP * TTOK];
__device__ int   g_tpe[TTOK * 2];    // (expert<<16)|pos per token slot
__device__ float g_tg[TTOK * 2];     // gates per token slot
__device__ float g_h[(size_t)2 * TTOK * HIDX];               // fp32 hidden
__device__ signed char g_hq[(size_t)2 * TTOK * HIDX];        // int8 hidden
__device__ float g_deqh[2 * TTOK];
__device__ int g_yp0[(size_t)2 * TTOK * DIMX];               // int32 partial (K half 0)
__device__ int g_yp1[(size_t)2 * TTOK * DIMX];               // int32 partial (K half 1)

// ---------------- helpers ----------------
__device__ __forceinline__ signed char terq(float x) {
    float r = rintf(x);
    r = fminf(1.f, fmaxf(-1.f, r));
    return (signed char)(int)r;
}
__device__ __forceinline__ signed char qi8(float x) {
    float r = rintf(x);
    r = fminf(127.f, fmaxf(-128.f, r));
    return (signed char)(int)r;
}
__device__ __forceinline__ uint32_t s2u(const void* p) {
    uint32_t a;
    asm("{ .reg .u64 t; cvta.to.shared.u64 t, %1; cvt.u32.u64 %0, t; }" : "=r"(a) : "l"(p));
    return a;
}
__device__ __forceinline__ void ldsm4(unsigned& r0, unsigned& r1, unsigned& r2, unsigned& r3,
                                      uint32_t a) {
    asm volatile("ldmatrix.sync.aligned.m8n8.x4.shared.b16 {%0,%1,%2,%3}, [%4];"
                 : "=r"(r0), "=r"(r1), "=r"(r2), "=r"(r3) : "r"(a));
}

// w2 ternarize slice: covers float4 range [sid*1024, sid*1024+1024)
__device__ __forceinline__ void w2_slice(const float4* __restrict__ w2v, int sid, int tid) {
    size_t base = (size_t)sid * 1024;
    #pragma unroll
    for (int j = 0; j < 4; j++) {
        size_t i = base + tid + j * 256;
        int e = (int)(i >> 20);                 // 1048576 float4 per expert
        float sc = 1.0f / g_mval[10 + e];
        float4 v = w2v[i];
        char4 c;
        c.x = terq(v.x * sc); c.y = terq(v.y * sc);
        c.z = terq(v.z * sc); c.w = terq(v.w * sc);
        ((char4*)g_wq2)[i] = c;
    }
}

// ---------------- 1) weight stats: per-tensor sum |w| ----------------
__global__ void stats_partial(const float* __restrict__ wr, const float* __restrict__ wn,
                              const float* __restrict__ w1, const float* __restrict__ w2) {
    int slot = blockIdx.y, chunk = blockIdx.x;
    const float4* p;
    int nvec;
    if (slot < 2) {
        if (chunk != 0) return;
        p = (const float4*)(slot ? wn : wr);
        nvec = NEXP * DIMX / 4;
    } else if (slot < 10) {
        p = (const float4*)(w1 + (size_t)(slot - 2) * HIDX * DIMX) + (size_t)chunk * 8192;
        nvec = 8192;
    } else {
        p = (const float4*)(w2 + (size_t)(slot - 10) * DIMX * HIDX) + (size_t)chunk * 8192;
        nvec = 8192;
    }
    float s = 0.f;
    for (int i = threadIdx.x; i < nvec; i += 256) {
        float4 v = p[i];
        s += fabsf(v.x) + fabsf(v.y) + fabsf(v.z) + fabsf(v.w);
    }
    __shared__ float sh[8];
    #pragma unroll
    for (int o = 16; o; o >>= 1) s += __shfl_xor_sync(0xffffffffu, s, o);
    if ((threadIdx.x & 31) == 0) sh[threadIdx.x >> 5] = s;
    __syncthreads();
    if (threadIdx.x == 0) {
        float t = 0.f;
        #pragma unroll
        for (int j = 0; j < 8; j++) t += sh[j];
        g_partial[slot * 128 + chunk] = t;
    }
}

// ---------------- 2) finalize: mvals + small-weight ternarize + zero counters ----------------
__global__ void finalize(const float* __restrict__ wr, const float* __restrict__ wn) {
    int tid = threadIdx.x;
    __shared__ float sm[18];
    if (tid < 18) {
        int nc = (tid < 2) ? 1 : 128;
        float sum = 0.f;
        for (int c = 0; c < nc; c++) sum += g_partial[tid * 128 + c];
        float nelem = (tid < 2) ? (float)(NEXP * DIMX) : (float)((size_t)HIDX * DIMX);
        float m = fmaxf(sum / nelem, 1e-5f);
        g_mval[tid] = m;
        sm[tid] = m;
    }
    if (tid < NEXP) g_cnt[tid] = 0;
    if (tid < 2) g_work[tid] = 0;
    __syncthreads();
    float sc0 = 1.0f / sm[0], sc1 = 1.0f / sm[1];
    for (int i = tid; i < NEXP * DIMX; i += 256) {
        g_wqr[i] = terq(wr[i] * sc0);
        g_wqn[i] = terq(wn[i] * sc1);
    }
}

// ---------------- 3) mega: w1 ternarize (z=0) + act-quant+router (z=1) ----------------
__global__ __launch_bounds__(256) void mega(const float* __restrict__ w1,
                                            const float* __restrict__ x,
                                            const float* __restrict__ eps) {
    int z = blockIdx.z;
    int tid = threadIdx.x;
    if (z == 0) {
        size_t i = (size_t)blockIdx.x * 256 + tid;   // float4 index, exactly covers w1
        int e = (int)(i >> 20);
        float sc = 1.0f / g_mval[2 + e];
        float4 v = ((const float4*)w1)[i];
        char4 c;
        c.x = terq(v.x * sc); c.y = terq(v.y * sc); c.z = terq(v.z * sc); c.w = terq(v.w * sc);
        ((char4*)g_wq1)[i] = c;
        return;
    }
    int t = blockIdx.x;
    if (t >= TTOK) return;

    __shared__ float shs[8], shm[8], svals[8], sdq[1];
    __shared__ int sx[256];

    float4 v = ((const float4*)(x + (size_t)t * DIMX))[tid];
    float ss = v.x * v.x + v.y * v.y + v.z * v.z + v.w * v.w;
    float am = fmaxf(fmaxf(fabsf(v.x), fabsf(v.y)), fmaxf(fabsf(v.z), fabsf(v.w)));
    #pragma unroll
    for (int o = 16; o; o >>= 1) {
        ss += __shfl_xor_sync(0xffffffffu, ss, o);
        am = fmaxf(am, __shfl_xor_sync(0xffffffffu, am, o));
    }
    if ((tid & 31) == 0) { shs[tid >> 5] = ss; shm[tid >> 5] = am; }
    __syncthreads();
    float tss = 0.f, tam = 0.f;
    #pragma unroll
    for (int j = 0; j < 8; j++) { tss += shs[j]; tam = fmaxf(tam, shm[j]); }
    float rs = rsqrtf(tss / (float)DIMX + 1e-6f);
    float a = fmaxf(tam * rs, 1e-5f);
    float sc = 127.0f / a;
    if (tid == 0) { g_deqx[t] = a / 127.0f; sdq[0] = a / 127.0f; }
    char4 c;
    c.x = qi8(v.x * rs * sc); c.y = qi8(v.y * rs * sc);
    c.z = qi8(v.z * rs * sc); c.w = qi8(v.w * rs * sc);
    ((char4*)(g_xq + (size_t)t * DIMX))[tid] = c;
    int ci;
    memcpy(&ci, &c, 4);
    sx[tid] = ci;
    __syncthreads();

    // router: warp w handles expert w
    int w = tid >> 5, lane = tid & 31;
    const int* wrp = (const int*)(g_wqr + w * DIMX);
    const int* wnp = (const int*)(g_wqn + w * DIMX);
    int ar = 0, an = 0;
    #pragma unroll
    for (int j = 0; j < 8; j++) {
        int xi = sx[lane + 32 * j];
        ar = __dp4a(xi, wrp[lane + 32 * j], ar);
        an = __dp4a(xi, wnp[lane + 32 * j], an);
    }
    #pragma unroll
    for (int o = 16; o; o >>= 1) {
        ar += __shfl_xor_sync(0xffffffffu, ar, o);
        an += __shfl_xor_sync(0xffffffffu, an, o);
    }
    if (lane == 0) {
        float dq = sdq[0];
        float lg = (float)ar * dq * g_mval[0];
        float nl = (float)an * dq * g_mval[1];
        float sp = fmaxf(nl, 0.f) + log1pf(expf(-fabsf(nl)));
        svals[w] = lg + eps[t * NEXP + w] * sp;
    }
    __syncthreads();
    if (tid == 0) {
        float v0 = -1e30f, v1 = -1e30f;
        int i0 = 0, i1 = 0;
        #pragma unroll
        for (int e = 0; e < NEXP; e++) {
            float vv = svals[e];
            if (vv > v0) { v1 = v0; i1 = i0; v0 = vv; i0 = e; }
            else if (vv > v1) { v1 = vv; i1 = e; }
        }
        float ex = expf(v1 - v0);
        float inv = 1.0f / (1.0f + ex);
        int p0 = atomicAdd(&g_cnt[i0], 1);
        g_tok[i0 * TTOK + p0] = t;
        int p1 = atomicAdd(&g_cnt[i1], 1);
        g_tok[i1 * TTOK + p1] = t;
        g_tpe[t * 2]     = (i0 << 16) | p0;
        g_tpe[t * 2 + 1] = (i1 << 16) | p1;
        g_tg[t * 2]      = inv;
        g_tg[t * 2 + 1]  = ex * inv;
    }
}

// ---------------- 4/6) PERSISTENT pipelined int8 tensor-core grouped GEMM ----------------
// Tile 128x128, BKK=64, 3-stage cp.async pipeline, grid=444 persistent blocks
// with atomic work stealing (each tile writes a disjoint region -> deterministic).
// MODE 1: work item = (e, mtile, ntile of 32); w2 ternarize swept after loop.
// MODE 2: work item = (e, mtile, ntile of 8, ksp of 2) -> int32 partial buffers.
#define BM 128
#define BN 128
#define BKK 64
#define LDSS 80          // 64 + 16 pad: conflict-free ldmatrix phases
#define STG_STRIDE (2 * BM * LDSS)   // A stage + B stage = 20480
#define GSMEM (3 * STG_STRIDE)       // 3 stages = 61440 B

__device__ __forceinline__ void mma8(int (&c)[4], const unsigned (&a)[4], const unsigned (&b)[2]) {
    asm volatile(
        "mma.sync.aligned.m16n8k32.row.col.s32.s8.s8.s32 "
        "{%0,%1,%2,%3}, {%4,%5,%6,%7}, {%8,%9}, {%0,%1,%2,%3};\n"
        : "+r"(c[0]), "+r"(c[1]), "+r"(c[2]), "+r"(c[3])
        : "r"(a[0]), "r"(a[1]), "r"(a[2]), "r"(a[3]), "r"(b[0]), "r"(b[1]));
}

template <int MODE>
__global__ __launch_bounds__(256, 3) void bit_gemm(const float* __restrict__ w2fp) {
    constexpr int K = (MODE == 1) ? DIMX : HIDX;          // full row stride
    constexpr int KRUN = (MODE == 1) ? DIMX : HIDX / 2;   // K covered per tile
    constexpr int N = (MODE == 1) ? HIDX : DIMX;
    constexpr int NITER = KRUN / BKK;
    constexpr int IPM = (MODE == 1) ? 32 : 16;            // items per mtile

    extern __shared__ char dsm[];
    const uint32_t smb = s2u(dsm);
    __shared__ int scnt[NEXP], soffv[NEXP], stot, swidx;

    const int tid = threadIdx.x;
    if (tid < NEXP) scnt[tid] = g_cnt[tid];
    __syncthreads();
    if (tid == 0) {
        int o = 0, tt = 0;
        #pragma unroll
        for (int e2 = 0; e2 < NEXP; e2++) {
            soffv[e2] = o;
            o += scnt[e2];
            tt += ((scnt[e2] + BM - 1) / BM) * IPM;
        }
        stot = tt;
    }
    __syncthreads();
    const int total = stot;

    const int lane = tid & 31, warp = tid >> 5;
    const int wm = warp >> 2, wn = warp & 3;   // 2x4 warp grid, warp tile 64x32
    const int lr = tid >> 1;                   // staged row (0..127)
    const int lcb = (tid & 1) * 32;            // byte offset within 64B k-chunk
    const uint32_t cpOff = (uint32_t)(lr * LDSS + lcb);
    const uint32_t aLO = (uint32_t)((lane & 15) * LDSS + (lane >> 4) * 16);
    const uint32_t bLO = (uint32_t)(((lane >> 4) * 8 + (lane & 7)) * LDSS + ((lane >> 3) & 1) * 16);

    while (true) {
        if (tid == 0) swidx = atomicAdd(&g_work[MODE - 1], 1);
        __syncthreads();
        const int widx = swidx;
        if (widx >= total) break;

        // decode (e, mtile, ntile, ksp)
        int rem = widx, e = 0;
        #pragma unroll
        for (int e2 = 0; e2 < NEXP; e2++) {
            int items = ((scnt[e2] + BM - 1) / BM) * IPM;
            if (rem >= items && e == e2) { rem -= items; e = e2 + 1; }
        }
        const int cnt = scnt[e];
        const int off = soffv[e];
        int mtile, ntile, ksp;
        if (MODE == 1) { mtile = rem >> 5; ntile = rem & 31; ksp = 0; }
        else { mtile = rem >> 4; int r2 = rem & 15; ntile = r2 >> 1; ksp = r2 & 1; }
        const int m0 = mtile * BM;
        const int n0 = ntile * BN;
        const int kbase = ksp * KRUN;

        int acc[4][4][4];
        #pragma unroll
        for (int a = 0; a < 4; a++)
            #pragma unroll
            for (int b = 0; b < 4; b++)
                #pragma unroll
                for (int c = 0; c < 4; c++) acc[a][b][c] = 0;

        const bool aok = (m0 + lr) < cnt;
        const signed char* Ap;
        if (MODE == 1) {
            int tok = aok ? g_tok[e * TTOK + m0 + lr] : 0;
            Ap = g_xq + (size_t)tok * K + kbase + lcb;
        } else {
            int r = aok ? (off + m0 + lr) : 0;
            Ap = g_hq + (size_t)r * K + kbase + lcb;
        }
        const unsigned aSz = aok ? 16u : 0u;
        const signed char* wsrc = (MODE == 1) ? g_wq1 : g_wq2;
        const signed char* Bp = wsrc + (size_t)e * N * K + (size_t)(n0 + lr) * K + kbase + lcb;

        auto prefetch = [&](int it) {
            int s = it;
            while (s >= 3) s -= 3;
            uint32_t ab = smb + s * STG_STRIDE + cpOff;
            uint32_t bb = ab + BM * LDSS;
            const signed char* as = Ap + it * BKK;
            const signed char* bs = Bp + it * BKK;
            asm volatile("cp.async.cg.shared.global [%0], [%1], 16, %2;"
                         :: "r"(ab), "l"(as), "r"(aSz) : "memory");
            asm volatile("cp.async.cg.shared.global [%0], [%1], 16, %2;"
                         :: "r"(ab + 16), "l"(as + 16), "r"(aSz) : "memory");
            asm volatile("cp.async.cg.shared.global [%0], [%1], 16, 16;"
                         :: "r"(bb), "l"(bs) : "memory");
            asm volatile("cp.async.cg.shared.global [%0], [%1], 16, 16;"
                         :: "r"(bb + 16), "l"(bs + 16) : "memory");
            asm volatile("cp.async.commit_group;" ::: "memory");
        };

        prefetch(0);
        prefetch(1);
        #pragma unroll 1
        for (int i = 0; i < NITER; i++) {
            // stage (i+2)%3 == (i-1)%3 was released by trailing barrier of iter i-1
            if (i + 2 < NITER) {
                prefetch(i + 2);
                asm volatile("cp.async.wait_group 2;" ::: "memory");
            } else if (i + 1 < NITER) {
                asm volatile("cp.async.wait_group 1;" ::: "memory");
            } else {
                asm volatile("cp.async.wait_group 0;" ::: "memory");
            }
            __syncthreads();                     // everyone's group-i copies landed
            int s = i;
            while (s >= 3) s -= 3;
            const uint32_t aB = smb + s * STG_STRIDE;
            const uint32_t bB = aB + BM * LDSS;
            #pragma unroll
            for (int ks = 0; ks < 2; ks++) {
                unsigned af[4][4];
                #pragma unroll
                for (int mi = 0; mi < 4; mi++)
                    ldsm4(af[mi][0], af[mi][1], af[mi][2], af[mi][3],
                          aB + (uint32_t)((wm * 64 + mi * 16) * LDSS + ks * 32) + aLO);
                unsigned bf[4][2];
                #pragma unroll
                for (int np = 0; np < 2; np++)
                    ldsm4(bf[np * 2][0], bf[np * 2][1], bf[np * 2 + 1][0], bf[np * 2 + 1][1],
                          bB + (uint32_t)((wn * 32 + np * 16) * LDSS + ks * 32) + bLO);
                #pragma unroll
                for (int mi = 0; mi < 4; mi++)
                    #pragma unroll
                    for (int ni = 0; ni < 4; ni++) mma8(acc[mi][ni], af[mi], bf[ni]);
            }
            __syncthreads();                     // release stage i for reuse
        }

        if (MODE == 1) {
            const float m1 = g_mval[2 + e];
            #pragma unroll
            for (int mi = 0; mi < 4; mi++) {
                #pragma unroll
                for (int half = 0; half < 2; half++) {
                    int rrow = wm * 64 + mi * 16 + (lane >> 2) + half * 8;
                    int pos = m0 + rrow;
                    if (pos < cnt) {
                        float d = g_deqx[g_tok[e * TTOK + pos]] * m1;
                        float* hrow = g_h + (size_t)(off + pos) * HIDX + n0;
                        #pragma unroll
                        for (int ni = 0; ni < 4; ni++) {
                            int col = wn * 32 + ni * 8 + (lane & 3) * 2;
                            float2 v;
                            v.x = fmaxf(0.f, (float)acc[mi][ni][half * 2 + 0] * d);
                            v.y = fmaxf(0.f, (float)acc[mi][ni][half * 2 + 1] * d);
                            *(float2*)(hrow + col) = v;
                        }
                    }
                }
            }
        } else {
            int* yp = ksp ? g_yp1 : g_yp0;
            #pragma unroll
            for (int mi = 0; mi < 4; mi++) {
                #pragma unroll
                for (int half = 0; half < 2; half++) {
                    int rrow = wm * 64 + mi * 16 + (lane >> 2) + half * 8;
                    int pos = m0 + rrow;
                    if (pos < cnt) {
                        int* yrow = yp + (size_t)(off + pos) * DIMX + n0;
                        #pragma unroll
                        for (int ni = 0; ni < 4; ni++) {
                            int col = wn * 32 + ni * 8 + (lane & 3) * 2;
                            int2 v;
                            v.x = acc[mi][ni][half * 2 + 0];
                            v.y = acc[mi][ni][half * 2 + 1];
                            *(int2*)(yrow + col) = v;
                        }
                    }
                }
            }
        }
        __syncthreads();   // all reads of swidx/tile state done before next claim
    }

    // MODE 1: sweep w2 ternarization across persistent blocks (uniform work)
    if (MODE == 1) {
        for (int s = blockIdx.x; s < 8192; s += NPERS)
            w2_slice((const float4*)w2fp, s, tid);
    }
}

// ---------------- 5) hidden quant: one block per packed row ----------------
__global__ void h_quant() {
    size_t row = blockIdx.x;   // 0 .. 2*TTOK-1 (all slots always filled)
    const float4* hp = (const float4*)(g_h + row * HIDX);
    int tid = threadIdx.x;
    float4 r[4];
    float ss = 0.f, am = 0.f;
    #pragma unroll
    for (int j = 0; j < 4; j++) {
        r[j] = hp[tid + 256 * j];
        ss += r[j].x * r[j].x + r[j].y * r[j].y + r[j].z * r[j].z + r[j].w * r[j].w;
        am = fmaxf(am, fmaxf(fmaxf(fabsf(r[j].x), fabsf(r[j].y)), fmaxf(fabsf(r[j].z), fabsf(r[j].w))));
    }
    __shared__ float shs[8], shm[8];
    #pragma unroll
    for (int o = 16; o; o >>= 1) {
        ss += __shfl_xor_sync(0xffffffffu, ss, o);
        am = fmaxf(am, __shfl_xor_sync(0xffffffffu, am, o));
    }
    if ((tid & 31) == 0) { shs[tid >> 5] = ss; shm[tid >> 5] = am; }
    __syncthreads();
    float tss = 0.f, tam = 0.f;
    #pragma unroll
    for (int j = 0; j < 8; j++) { tss += shs[j]; tam = fmaxf(tam, shm[j]); }
    float rs = rsqrtf(tss / (float)HIDX + 1e-6f);
    float a = fmaxf(tam * rs, 1e-5f);
    float sc = 127.0f / a;
    if (tid == 0) g_deqh[row] = a / 127.0f;
    char4* dst = (char4*)(g_hq + row * HIDX);
    #pragma unroll
    for (int j = 0; j < 4; j++) {
        char4 c;
        c.x = qi8(r[j].x * rs * sc); c.y = qi8(r[j].y * rs * sc);
        c.z = qi8(r[j].z * rs * sc); c.w = qi8(r[j].w * rs * sc);
        dst[tid + 256 * j] = c;
    }
}

// ---------------- 7) gated combine (deterministic, atomic-free) ----------------
__global__ void combine(float* __restrict__ out) {
    __shared__ int soff[NEXP];
    int t = blockIdx.x, i = threadIdx.x;
    if (i == 0) {
        int o = 0;
        #pragma unroll
        for (int j = 0; j < NEXP; j++) { soff[j] = o; o += g_cnt[j]; }
    }
    __syncthreads();
    int a0 = g_tpe[t * 2], a1 = g_tpe[t * 2 + 1];
    int e0 = a0 >> 16, e1 = a1 >> 16;
    int row0 = soff[e0] + (a0 & 0xFFFF);
    int row1 = soff[e1] + (a1 & 0xFFFF);
    float d0 = g_deqh[row0] * g_mval[10 + e0] * g_tg[t * 2];
    float d1 = g_deqh[row1] * g_mval[10 + e1] * g_tg[t * 2 + 1];
    size_t r0 = (size_t)row0 * DIMX;
    size_t r1 = (size_t)row1 * DIMX;
    int4 p00 = ((const int4*)(g_yp0 + r0))[i];
    int4 p01 = ((const int4*)(g_yp1 + r0))[i];
    int4 p10 = ((const int4*)(g_yp0 + r1))[i];
    int4 p11 = ((const int4*)(g_yp1 + r1))[i];
    float4 o;
    o.x = (float)(p00.x + p01.x) * d0 + (float)(p10.x + p11.x) * d1;
    o.y = (float)(p00.y + p01.y) * d0 + (float)(p10.y + p11.y) * d1;
    o.z = (float)(p00.z + p01.z) * d0 + (float)(p10.z + p11.z) * d1;
    o.w = (float)(p00.w + p01.w) * d0 + (float)(p10.w + p11.w) * d1;
    ((float4*)(out + (size_t)t * DIMX))[i] = o;
}

// ---------------- launch ----------------
extern "C" void kernel_launch(void* const* d_in, const int* in_sizes, int n_in,
                              void* d_out, int out_size) {
    const float* x   = (const float*)d_in[0];
    const float* eps = (const float*)d_in[1];
    const float* wr  = (const float*)d_in[2];
    const float* wn  = (const float*)d_in[3];
    const float* w1  = (const float*)d_in[4];
    const float* w2  = (const float*)d_in[5];
    float* out = (float*)d_out;

    cudaFuncSetAttribute(bit_gemm<1>, cudaFuncAttributeMaxDynamicSharedMemorySize, GSMEM);
    cudaFuncSetAttribute(bit_gemm<2>, cudaFuncAttributeMaxDynamicSharedMemorySize, GSMEM);

    stats_partial<<<dim3(128, 18), 256>>>(wr, wn, w1, w2);      // 1
    finalize<<<1, 256>>>(wr, wn);                               // 2
    mega<<<dim3(32768, 1, 2), 256>>>(w1, x, eps);               // 3
    bit_gemm<1><<<NPERS, 256, GSMEM>>>(w2);                     // 4 <- profiled (persistent)
    h_quant<<<2 * TTOK, 256>>>();                               // 5
    bit_gemm<2><<<NPERS, 256, GSMEM>>>(nullptr);                // 6 (persistent, K-split)
    combine<<<TTOK, 256>>>(out);                                // 7
}

// round 14
// speedup vs baseline: 1.1629x; 1.0823x over previous
#include <cuda_runtime.h>
#include <cstdint>

#define DIMX 1024
#define NEXP 8
#define HIDX 4096
#define TTOK 4096   // B*S = 2*2048

// ---------------- static scratch (no allocations allowed) ----------------
__device__ signed char g_wq1[(size_t)NEXP * HIDX * DIMX];   // ternary w1
__device__ signed char g_wq2[(size_t)NEXP * DIMX * HIDX];   // ternary w2
__device__ signed char g_wqr[NEXP * DIMX];
__device__ signed char g_wqn[NEXP * DIMX];
__device__ float g_partial[18 * 128];
__device__ float g_mval[18];
__device__ signed char g_xq[(size_t)TTOK * DIMX];
__device__ float g_deqx[TTOK];
__device__ int   g_cnt[NEXP];
__device__ int   g_tok[NEXP * TTOK];
__device__ int   g_tpe[TTOK * 2];    // (expert<<16)|pos per token slot
__device__ float g_tg[TTOK * 2];     // gates per token slot
__device__ float g_h[(size_t)2 * TTOK * HIDX];               // fp32 hidden
__device__ signed char g_hq[(size_t)2 * TTOK * HIDX];        // int8 hidden
__device__ float g_deqh[2 * TTOK];
__device__ int g_yp0[(size_t)2 * TTOK * DIMX];               // int32 partial (K half 0)
__device__ int g_yp1[(size_t)2 * TTOK * DIMX];               // int32 partial (K half 1)

// ---------------- helpers ----------------
__device__ __forceinline__ signed char terq(float x) {
    float r = rintf(x);
    r = fminf(1.f, fmaxf(-1.f, r));
    return (signed char)(int)r;
}
__device__ __forceinline__ signed char qi8(float x) {
    float r = rintf(x);
    r = fminf(127.f, fmaxf(-128.f, r));
    return (signed char)(int)r;
}
__device__ __forceinline__ uint32_t s2u(const void* p) {
    uint32_t a;
    asm("{ .reg .u64 t; cvta.to.shared.u64 t, %1; cvt.u32.u64 %0, t; }" : "=r"(a) : "l"(p));
    return a;
}
__device__ __forceinline__ void ldsm4(unsigned& r0, unsigned& r1, unsigned& r2, unsigned& r3,
                                      uint32_t a) {
    asm volatile("ldmatrix.sync.aligned.m8n8.x4.shared.b16 {%0,%1,%2,%3}, [%4];"
                 : "=r"(r0), "=r"(r1), "=r"(r2), "=r"(r3) : "r"(a));
}

// w2 ternarize slice: covers float4 range [sid*1024, sid*1024+1024)
__device__ __forceinline__ void w2_slice(const float4* __restrict__ w2v, int sid, int tid) {
    size_t base = (size_t)sid * 1024;
    #pragma unroll
    for (int j = 0; j < 4; j++) {
        size_t i = base + tid + j * 256;
        int e = (int)(i >> 20);                 // 1048576 float4 per expert
        float sc = 1.0f / g_mval[10 + e];
        float4 v = w2v[i];
        char4 c;
        c.x = terq(v.x * sc); c.y = terq(v.y * sc);
        c.z = terq(v.z * sc); c.w = terq(v.w * sc);
        ((char4*)g_wq2)[i] = c;
    }
}

// ---------------- 1) weight stats: per-tensor sum |w| ----------------
__global__ void stats_partial(const float* __restrict__ wr, const float* __restrict__ wn,
                              const float* __restrict__ w1, const float* __restrict__ w2) {
    int slot = blockIdx.y, chunk = blockIdx.x;
    const float4* p;
    int nvec;
    if (slot < 2) {
        if (chunk != 0) return;
        p = (const float4*)(slot ? wn : wr);
        nvec = NEXP * DIMX / 4;
    } else if (slot < 10) {
        p = (const float4*)(w1 + (size_t)(slot - 2) * HIDX * DIMX) + (size_t)chunk * 8192;
        nvec = 8192;
    } else {
        p = (const float4*)(w2 + (size_t)(slot - 10) * DIMX * HIDX) + (size_t)chunk * 8192;
        nvec = 8192;
    }
    float s = 0.f;
    for (int i = threadIdx.x; i < nvec; i += 256) {
        float4 v = p[i];
        s += fabsf(v.x) + fabsf(v.y) + fabsf(v.z) + fabsf(v.w);
    }
    __shared__ float sh[8];
    #pragma unroll
    for (int o = 16; o; o >>= 1) s += __shfl_xor_sync(0xffffffffu, s, o);
    if ((threadIdx.x & 31) == 0) sh[threadIdx.x >> 5] = s;
    __syncthreads();
    if (threadIdx.x == 0) {
        float t = 0.f;
        #pragma unroll
        for (int j = 0; j < 8; j++) t += sh[j];
        g_partial[slot * 128 + chunk] = t;
    }
}

// ---------------- 2) finalize: mvals + small-weight ternarize + zero counters ----------------
__global__ void finalize(const float* __restrict__ wr, const float* __restrict__ wn) {
    int tid = threadIdx.x;
    __shared__ float sm[18];
    if (tid < 18) {
        int nc = (tid < 2) ? 1 : 128;
        float sum = 0.f;
        for (int c = 0; c < nc; c++) sum += g_partial[tid * 128 + c];
        float nelem = (tid < 2) ? (float)(NEXP * DIMX) : (float)((size_t)HIDX * DIMX);
        float m = fmaxf(sum / nelem, 1e-5f);
        g_mval[tid] = m;
        sm[tid] = m;
    }
    if (tid < NEXP) g_cnt[tid] = 0;
    __syncthreads();
    float sc0 = 1.0f / sm[0], sc1 = 1.0f / sm[1];
    for (int i = tid; i < NEXP * DIMX; i += 256) {
        g_wqr[i] = terq(wr[i] * sc0);
        g_wqn[i] = terq(wn[i] * sc1);
    }
}

// ---------------- 3) mega: w1 ternarize (z=0) + act-quant+router (z=1) ----------------
__global__ __launch_bounds__(256) void mega(const float* __restrict__ w1,
                                            const float* __restrict__ x,
                                            const float* __restrict__ eps) {
    int z = blockIdx.z;
    int tid = threadIdx.x;
    if (z == 0) {
        size_t i = (size_t)blockIdx.x * 256 + tid;   // float4 index, exactly covers w1
        int e = (int)(i >> 20);
        float sc = 1.0f / g_mval[2 + e];
        float4 v = ((const float4*)w1)[i];
        char4 c;
        c.x = terq(v.x * sc); c.y = terq(v.y * sc); c.z = terq(v.z * sc); c.w = terq(v.w * sc);
        ((char4*)g_wq1)[i] = c;
        return;
    }
    int t = blockIdx.x;
    if (t >= TTOK) return;

    __shared__ float shs[8], shm[8], svals[8], sdq[1];
    __shared__ int sx[256];

    float4 v = ((const float4*)(x + (size_t)t * DIMX))[tid];
    float ss = v.x * v.x + v.y * v.y + v.z * v.z + v.w * v.w;
    float am = fmaxf(fmaxf(fabsf(v.x), fabsf(v.y)), fmaxf(fabsf(v.z), fabsf(v.w)));
    #pragma unroll
    for (int o = 16; o; o >>= 1) {
        ss += __shfl_xor_sync(0xffffffffu, ss, o);
        am = fmaxf(am, __shfl_xor_sync(0xffffffffu, am, o));
    }
    if ((tid & 31) == 0) { shs[tid >> 5] = ss; shm[tid >> 5] = am; }
    __syncthreads();
    float tss = 0.f, tam = 0.f;
    #pragma unroll
    for (int j = 0; j < 8; j++) { tss += shs[j]; tam = fmaxf(tam, shm[j]); }
    float rs = rsqrtf(tss / (float)DIMX + 1e-6f);
    float a = fmaxf(tam * rs, 1e-5f);
    float sc = 127.0f / a;
    if (tid == 0) { g_deqx[t] = a / 127.0f; sdq[0] = a / 127.0f; }
    char4 c;
    c.x = qi8(v.x * rs * sc); c.y = qi8(v.y * rs * sc);
    c.z = qi8(v.z * rs * sc); c.w = qi8(v.w * rs * sc);
    ((char4*)(g_xq + (size_t)t * DIMX))[tid] = c;
    int ci;
    memcpy(&ci, &c, 4);
    sx[tid] = ci;
    __syncthreads();

    // router: warp w handles expert w
    int w = tid >> 5, lane = tid & 31;
    const int* wrp = (const int*)(g_wqr + w * DIMX);
    const int* wnp = (const int*)(g_wqn + w * DIMX);
    int ar = 0, an = 0;
    #pragma unroll
    for (int j = 0; j < 8; j++) {
        int xi = sx[lane + 32 * j];
        ar = __dp4a(xi, wrp[lane + 32 * j], ar);
        an = __dp4a(xi, wnp[lane + 32 * j], an);
    }
    #pragma unroll
    for (int o = 16; o; o >>= 1) {
        ar += __shfl_xor_sync(0xffffffffu, ar, o);
        an += __shfl_xor_sync(0xffffffffu, an, o);
    }
    if (lane == 0) {
        float dq = sdq[0];
        float lg = (float)ar * dq * g_mval[0];
        float nl = (float)an * dq * g_mval[1];
        float sp = fmaxf(nl, 0.f) + log1pf(expf(-fabsf(nl)));
        svals[w] = lg + eps[t * NEXP + w] * sp;
    }
    __syncthreads();
    if (tid == 0) {
        float v0 = -1e30f, v1 = -1e30f;
        int i0 = 0, i1 = 0;
        #pragma unroll
        for (int e = 0; e < NEXP; e++) {
            float vv = svals[e];
            if (vv > v0) { v1 = v0; i1 = i0; v0 = vv; i0 = e; }
            else if (vv > v1) { v1 = vv; i1 = e; }
        }
        float ex = expf(v1 - v0);
        float inv = 1.0f / (1.0f + ex);
        int p0 = atomicAdd(&g_cnt[i0], 1);
        g_tok[i0 * TTOK + p0] = t;
        int p1 = atomicAdd(&g_cnt[i1], 1);
        g_tok[i1 * TTOK + p1] = t;
        g_tpe[t * 2]     = (i0 << 16) | p0;
        g_tpe[t * 2 + 1] = (i1 << 16) | p1;
        g_tg[t * 2]      = inv;
        g_tg[t * 2 + 1]  = ex * inv;
    }
}

// ---------------- 4/6) HYBRID tensor+dp4a int8 grouped GEMM ----------------
// Tile 128x128: columns 0..95 via mma.sync (tensor pipe), columns 96..127 via
// dp4a (fma pipe) computed concurrently from the same smem stages. dp4a is
// bit-exact integer math -> results identical to the all-tensor version.
// 3-stage cp.async pipeline, two barriers per K-iter.
// MODE 2 uses a deterministic K-split into int32 partial buffers.
#define BM 128
#define BN 128
#define BKK 64
#define LDSS 80          // 64 + 16 pad
#define STG_STRIDE (2 * BM * LDSS)   // A stage + B stage = 20480
#define GSMEM (3 * STG_STRIDE)       // 3 stages = 61440 B

__device__ __forceinline__ void mma8(int (&c)[4], const unsigned (&a)[4], const unsigned (&b)[2]) {
    asm volatile(
        "mma.sync.aligned.m16n8k32.row.col.s32.s8.s8.s32 "
        "{%0,%1,%2,%3}, {%4,%5,%6,%7}, {%8,%9}, {%0,%1,%2,%3};\n"
        : "+r"(c[0]), "+r"(c[1]), "+r"(c[2]), "+r"(c[3])
        : "r"(a[0]), "r"(a[1]), "r"(a[2]), "r"(a[3]), "r"(b[0]), "r"(b[1]));
}

template <int MODE>
__global__ __launch_bounds__(256, 2) void bit_gemm(const float* __restrict__ w2fp) {
    constexpr int K = (MODE == 1) ? DIMX : HIDX;          // full row stride
    constexpr int KRUN = (MODE == 1) ? DIMX : HIDX / 2;   // K covered per block
    constexpr int N = (MODE == 1) ? HIDX : DIMX;
    constexpr int NITER = KRUN / BKK;
    const int e = (MODE == 1) ? blockIdx.z : (blockIdx.z & 7);
    const int ksp = (MODE == 1) ? 0 : (blockIdx.z >> 3);
    const int kbase = ksp * KRUN;
    const int cnt = g_cnt[e];
    const int m0 = blockIdx.y * BM;
    const int tid = threadIdx.x;
    if (m0 >= cnt) {
        if (MODE == 1) {
            int bid = blockIdx.x + (int)gridDim.x * (blockIdx.y + (int)gridDim.y * blockIdx.z);
            w2_slice((const float4*)w2fp, bid, tid);
        }
        return;
    }
    const int n0 = blockIdx.x * BN;
    int off = 0;
    #pragma unroll
    for (int j = 0; j < NEXP; j++) if (j < e) off += g_cnt[j];

    extern __shared__ char dsm[];
    const uint32_t smb = s2u(dsm);

    const int lane = tid & 31, warp = tid >> 5;
    const int wm = warp >> 2, wn = warp & 3;   // 2x4 warp grid

    // tensor: warp tile 64 rows x 24 cols (cols wn*24 .. +24)
    int acc[4][3][4];
    #pragma unroll
    for (int a = 0; a < 4; a++)
        #pragma unroll
        for (int b = 0; b < 3; b++)
            #pragma unroll
            for (int c = 0; c < 4; c++) acc[a][b][c] = 0;
    // dp4a: warp handles rows wm*64..+64 (2 per lane), cols 96 + wn*8 .. +8
    int dacc[2][8];
    #pragma unroll
    for (int a = 0; a < 2; a++)
        #pragma unroll
        for (int b = 0; b < 8; b++) dacc[a][b] = 0;

    const int lr = tid >> 1;            // staged row (0..127)
    const int lcb = (tid & 1) * 32;     // byte offset within 64B k-chunk
    const bool aok = (m0 + lr) < cnt;
    const signed char* Ap;
    if (MODE == 1) {
        int tok = aok ? g_tok[e * TTOK + m0 + lr] : 0;
        Ap = g_xq + (size_t)tok * K + kbase + lcb;
    } else {
        int r = aok ? (off + m0 + lr) : 0;
        Ap = g_hq + (size_t)r * K + kbase + lcb;
    }
    const unsigned aSz = aok ? 16u : 0u;
    const signed char* wsrc = (MODE == 1) ? g_wq1 : g_wq2;
    const signed char* Bp = wsrc + (size_t)e * N * K + (size_t)(n0 + lr) * K + kbase + lcb;

    const uint32_t cpOff = (uint32_t)(lr * LDSS + lcb);
    const uint32_t aLO = (uint32_t)((lane & 15) * LDSS + (lane >> 4) * 16);
    const uint32_t bLO = (uint32_t)(((lane >> 4) * 8 + (lane & 7)) * LDSS + ((lane >> 3) & 1) * 16);

    // dp4a row bases within stage (conflict-free: bank stride 20, distinct per 8-lane phase)
    const int dr0 = wm * 64 + lane;
    const int dr1 = wm * 64 + 32 + lane;

    auto prefetch = [&](int it) {
        int s = it;
        while (s >= 3) s -= 3;
        uint32_t ab = smb + s * STG_STRIDE + cpOff;
        uint32_t bb = ab + BM * LDSS;
        const signed char* as = Ap;
        const signed char* bs = Bp;
        unsigned asz = 0, bsz = 0;
        if (it < NITER) {
            as = Ap + it * BKK;
            bs = Bp + it * BKK;
            asz = aSz;
            bsz = 16;
        }
        asm volatile("cp.async.cg.shared.global [%0], [%1], 16, %2;"
                     :: "r"(ab), "l"(as), "r"(asz) : "memory");
        asm volatile("cp.async.cg.shared.global [%0], [%1], 16, %2;"
                     :: "r"(ab + 16), "l"(as + 16), "r"(asz) : "memory");
        asm volatile("cp.async.cg.shared.global [%0], [%1], 16, %2;"
                     :: "r"(bb), "l"(bs), "r"(bsz) : "memory");
        asm volatile("cp.async.cg.shared.global [%0], [%1], 16, %2;"
                     :: "r"(bb + 16), "l"(bs + 16), "r"(bsz) : "memory");
        asm volatile("cp.async.commit_group;" ::: "memory");
    };

    prefetch(0);
    prefetch(1);
    #pragma unroll 1
    for (int i = 0; i < NITER; i++) {
        prefetch(i + 2);
        asm volatile("cp.async.wait_group 2;" ::: "memory");   // my group-i copies landed
        __syncthreads();                                       // everyone's group-i copies landed
        int s = i;
        while (s >= 3) s -= 3;
        const uint32_t aB = smb + s * STG_STRIDE;
        const uint32_t bB = aB + BM * LDSS;
        const char* aSm = dsm + s * STG_STRIDE;
        const char* bSm = aSm + BM * LDSS;

        // tensor part: cols 0..95
        #pragma unroll
        for (int ks = 0; ks < 2; ks++) {
            unsigned af[4][4];
            #pragma unroll
            for (int mi = 0; mi < 4; mi++)
                ldsm4(af[mi][0], af[mi][1], af[mi][2], af[mi][3],
                      aB + (uint32_t)((wm * 64 + mi * 16) * LDSS + ks * 32) + aLO);
            unsigned bf[4][2];
            #pragma unroll
            for (int np = 0; np < 2; np++)
                ldsm4(bf[np * 2][0], bf[np * 2][1], bf[np * 2 + 1][0], bf[np * 2 + 1][1],
                      bB + (uint32_t)((wn * 24 + np * 16) * LDSS + ks * 32) + bLO);
            #pragma unroll
            for (int mi = 0; mi < 4; mi++)
                #pragma unroll
                for (int ni = 0; ni < 3; ni++) mma8(acc[mi][ni], af[mi], bf[ni]);
        }

        // dp4a part: cols 96..127 (fma pipe, concurrent with tensor pipe)
        #pragma unroll
        for (int kq = 0; kq < 4; kq++) {
            int4 a0 = *(const int4*)(aSm + dr0 * LDSS + kq * 16);
            int4 a1 = *(const int4*)(aSm + dr1 * LDSS + kq * 16);
            #pragma unroll
            for (int c = 0; c < 8; c++) {
                int4 bv = *(const int4*)(bSm + (96 + wn * 8 + c) * LDSS + kq * 16);
                int t0 = dacc[0][c], t1 = dacc[1][c];
                t0 = __dp4a(a0.x, bv.x, t0); t1 = __dp4a(a1.x, bv.x, t1);
                t0 = __dp4a(a0.y, bv.y, t0); t1 = __dp4a(a1.y, bv.y, t1);
                t0 = __dp4a(a0.z, bv.z, t0); t1 = __dp4a(a1.z, bv.z, t1);
                t0 = __dp4a(a0.w, bv.w, t0); t1 = __dp4a(a1.w, bv.w, t1);
                dacc[0][c] = t0; dacc[1][c] = t1;
            }
        }
        __syncthreads();                                       // release stage i for reuse
    }

    if (MODE == 1) {
        const float m1 = g_mval[2 + e];
        // tensor epilogue: cols 0..95
        #pragma unroll
        for (int mi = 0; mi < 4; mi++) {
            #pragma unroll
            for (int half = 0; half < 2; half++) {
                int rrow = wm * 64 + mi * 16 + (lane >> 2) + half * 8;
                int pos = m0 + rrow;
                if (pos < cnt) {
                    float d = g_deqx[g_tok[e * TTOK + pos]] * m1;
                    float* hrow = g_h + (size_t)(off + pos) * HIDX + n0;
                    #pragma unroll
                    for (int ni = 0; ni < 3; ni++) {
                        int col = wn * 24 + ni * 8 + (lane & 3) * 2;
                        float2 v;
                        v.x = fmaxf(0.f, (float)acc[mi][ni][half * 2 + 0] * d);
                        v.y = fmaxf(0.f, (float)acc[mi][ni][half * 2 + 1] * d);
                        *(float2*)(hrow + col) = v;
                    }
                }
            }
        }
        // dp4a epilogue: cols 96..127
        #pragma unroll
        for (int rr = 0; rr < 2; rr++) {
            int pos = m0 + wm * 64 + rr * 32 + lane;
            if (pos < cnt) {
                float d = g_deqx[g_tok[e * TTOK + pos]] * m1;
                float* hrow = g_h + (size_t)(off + pos) * HIDX + n0 + 96 + wn * 8;
                float4 v0, v1;
                v0.x = fmaxf(0.f, (float)dacc[rr][0] * d);
                v0.y = fmaxf(0.f, (float)dacc[rr][1] * d);
                v0.z = fmaxf(0.f, (float)dacc[rr][2] * d);
                v0.w = fmaxf(0.f, (float)dacc[rr][3] * d);
                v1.x = fmaxf(0.f, (float)dacc[rr][4] * d);
                v1.y = fmaxf(0.f, (float)dacc[rr][5] * d);
                v1.z = fmaxf(0.f, (float)dacc[rr][6] * d);
                v1.w = fmaxf(0.f, (float)dacc[rr][7] * d);
                *(float4*)(hrow) = v0;
                *(float4*)(hrow + 4) = v1;
            }
        }
        // this block's w2 ternarize slice (overlaps with other blocks' MMA work)
        int bid = blockIdx.x + (int)gridDim.x * (blockIdx.y + (int)gridDim.y * blockIdx.z);
        w2_slice((const float4*)w2fp, bid, tid);
    } else {
        int* yp = ksp ? g_yp1 : g_yp0;
        #pragma unroll
        for (int mi = 0; mi < 4; mi++) {
            #pragma unroll
            for (int half = 0; half < 2; half++) {
                int rrow = wm * 64 + mi * 16 + (lane >> 2) + half * 8;
                int pos = m0 + rrow;
                if (pos < cnt) {
                    int* yrow = yp + (size_t)(off + pos) * DIMX + n0;
                    #pragma unroll
                    for (int ni = 0; ni < 3; ni++) {
                        int col = wn * 24 + ni * 8 + (lane & 3) * 2;
                        int2 v;
                        v.x = acc[mi][ni][half * 2 + 0];
                        v.y = acc[mi][ni][half * 2 + 1];
                        *(int2*)(yrow + col) = v;
                    }
                }
            }
        }
        #pragma unroll
        for (int rr = 0; rr < 2; rr++) {
            int pos = m0 + wm * 64 + rr * 32 + lane;
            if (pos < cnt) {
                int* yrow = yp + (size_t)(off + pos) * DIMX + n0 + 96 + wn * 8;
                int4 v0, v1;
                v0.x = dacc[rr][0]; v0.y = dacc[rr][1]; v0.z = dacc[rr][2]; v0.w = dacc[rr][3];
                v1.x = dacc[rr][4]; v1.y = dacc[rr][5]; v1.z = dacc[rr][6]; v1.w = dacc[rr][7];
                *(int4*)(yrow) = v0;
                *(int4*)(yrow + 4) = v1;
            }
        }
    }
}

// ---------------- 5) hidden quant: one block per packed row ----------------
__global__ void h_quant() {
    size_t row = blockIdx.x;   // 0 .. 2*TTOK-1 (all slots always filled)
    const float4* hp = (const float4*)(g_h + row * HIDX);
    int tid = threadIdx.x;
    float4 r[4];
    float ss = 0.f, am = 0.f;
    #pragma unroll
    for (int j = 0; j < 4; j++) {
        r[j] = hp[tid + 256 * j];
        ss += r[j].x * r[j].x + r[j].y * r[j].y + r[j].z * r[j].z + r[j].w * r[j].w;
        am = fmaxf(am, fmaxf(fmaxf(fabsf(r[j].x), fabsf(r[j].y)), fmaxf(fabsf(r[j].z), fabsf(r[j].w))));
    }
    __shared__ float shs[8], shm[8];
    #pragma unroll
    for (int o = 16; o; o >>= 1) {
        ss += __shfl_xor_sync(0xffffffffu, ss, o);
        am = fmaxf(am, __shfl_xor_sync(0xffffffffu, am, o));
    }
    if ((tid & 31) == 0) { shs[tid >> 5] = ss; shm[tid >> 5] = am; }
    __syncthreads();
    float tss = 0.f, tam = 0.f;
    #pragma unroll
    for (int j = 0; j < 8; j++) { tss += shs[j]; tam = fmaxf(tam, shm[j]); }
    float rs = rsqrtf(tss / (float)HIDX + 1e-6f);
    float a = fmaxf(tam * rs, 1e-5f);
    float sc = 127.0f / a;
    if (tid == 0) g_deqh[row] = a / 127.0f;
    char4* dst = (char4*)(g_hq + row * HIDX);
    #pragma unroll
    for (int j = 0; j < 4; j++) {
        char4 c;
        c.x = qi8(r[j].x * rs * sc); c.y = qi8(r[j].y * rs * sc);
        c.z = qi8(r[j].z * rs * sc); c.w = qi8(r[j].w * rs * sc);
        dst[tid + 256 * j] = c;
    }
}

// ---------------- 7) gated combine (deterministic, atomic-free) ----------------
__global__ void combine(float* __restrict__ out) {
    __shared__ int soff[NEXP];
    int t = blockIdx.x, i = threadIdx.x;
    if (i == 0) {
        int o = 0;
        #pragma unroll
        for (int j = 0; j < NEXP; j++) { soff[j] = o; o += g_cnt[j]; }
    }
    __syncthreads();
    int a0 = g_tpe[t * 2], a1 = g_tpe[t * 2 + 1];
    int e0 = a0 >> 16, e1 = a1 >> 16;
    int row0 = soff[e0] + (a0 & 0xFFFF);
    int row1 = soff[e1] + (a1 & 0xFFFF);
    float d0 = g_deqh[row0] * g_mval[10 + e0] * g_tg[t * 2];
    float d1 = g_deqh[row1] * g_mval[10 + e1] * g_tg[t * 2 + 1];
    size_t r0 = (size_t)row0 * DIMX;
    size_t r1 = (size_t)row1 * DIMX;
    int4 p00 = ((const int4*)(g_yp0 + r0))[i];
    int4 p01 = ((const int4*)(g_yp1 + r0))[i];
    int4 p10 = ((const int4*)(g_yp0 + r1))[i];
    int4 p11 = ((const int4*)(g_yp1 + r1))[i];
    float4 o;
    o.x = (float)(p00.x + p01.x) * d0 + (float)(p10.x + p11.x) * d1;
    o.y = (float)(p00.y + p01.y) * d0 + (float)(p10.y + p11.y) * d1;
    o.z = (float)(p00.z + p01.z) * d0 + (float)(p10.z + p11.z) * d1;
    o.w = (float)(p00.w + p01.w) * d0 + (float)(p10.w + p11.w) * d1;
    ((float4*)(out + (size_t)t * DIMX))[i] = o;
}

// ---------------- launch ----------------
extern "C" void kernel_launch(void* const* d_in, const int* in_sizes, int n_in,
                              void* d_out, int out_size) {
    const float* x   = (const float*)d_in[0];
    const float* eps = (const float*)d_in[1];
    const float* wr  = (const float*)d_in[2];
    const float* wn  = (const float*)d_in[3];
    const float* w1  = (const float*)d_in[4];
    const float* w2  = (const float*)d_in[5];
    float* out = (float*)d_out;

    cudaFuncSetAttribute(bit_gemm<1>, cudaFuncAttributeMaxDynamicSharedMemorySize, GSMEM);
    cudaFuncSetAttribute(bit_gemm<2>, cudaFuncAttributeMaxDynamicSharedMemorySize, GSMEM);

    stats_partial<<<dim3(128, 18), 256>>>(wr, wn, w1, w2);      // 1
    finalize<<<1, 256>>>(wr, wn);                               // 2
    mega<<<dim3(32768, 1, 2), 256>>>(w1, x, eps);               // 3
    bit_gemm<1><<<dim3(HIDX / BN, TTOK / BM, NEXP), 256, GSMEM>>>(w2);   // 4 <- profiled (hybrid)
    h_quant<<<2 * TTOK, 256>>>();                               // 5
    bit_gemm<2><<<dim3(DIMX / BN, TTOK / BM, NEXP * 2), 256, GSMEM>>>(nullptr);  // 6 (K-split)
    combine<<<TTOK, 256>>>(out);                                // 7
}

// round 15
// speedup vs baseline: 1.2006x; 1.0324x over previous
#include <cuda_runtime.h>
#include <cstdint>

#define DIMX 1024
#define NEXP 8
#define HIDX 4096
#define TTOK 4096   // B*S = 2*2048

// ---------------- static scratch (no allocations allowed) ----------------
__device__ signed char g_wq1[(size_t)NEXP * HIDX * DIMX];   // ternary w1
__device__ signed char g_wq2[(size_t)NEXP * DIMX * HIDX];   // ternary w2
__device__ signed char g_wqr[NEXP * DIMX];
__device__ signed char g_wqn[NEXP * DIMX];
__device__ float g_partial[18 * 128];
__device__ float g_mval[18];
__device__ signed char g_xq[(size_t)TTOK * DIMX];
__device__ float g_deqx[TTOK];
__device__ int   g_cnt[NEXP];
__device__ int   g_tok[NEXP * TTOK];
__device__ int   g_tpe[TTOK * 2];    // (expert<<16)|pos per token slot
__device__ float g_tg[TTOK * 2];     // gates per token slot
__device__ float g_h[(size_t)2 * TTOK * HIDX];               // fp32 hidden
__device__ signed char g_hq[(size_t)2 * TTOK * HIDX];        // int8 hidden
__device__ float g_deqh[2 * TTOK];
__device__ int g_yp0[(size_t)2 * TTOK * DIMX];               // int32 partial (K half 0)
__device__ int g_yp1[(size_t)2 * TTOK * DIMX];               // int32 partial (K half 1)

// ---------------- helpers ----------------
__device__ __forceinline__ signed char terq(float x) {
    float r = rintf(x);
    r = fminf(1.f, fmaxf(-1.f, r));
    return (signed char)(int)r;
}
__device__ __forceinline__ signed char qi8(float x) {
    float r = rintf(x);
    r = fminf(127.f, fmaxf(-128.f, r));
    return (signed char)(int)r;
}
__device__ __forceinline__ uint32_t s2u(const void* p) {
    uint32_t a;
    asm("{ .reg .u64 t; cvta.to.shared.u64 t, %1; cvt.u32.u64 %0, t; }" : "=r"(a) : "l"(p));
    return a;
}
__device__ __forceinline__ void ldsm4(unsigned& r0, unsigned& r1, unsigned& r2, unsigned& r3,
                                      uint32_t a) {
    asm volatile("ldmatrix.sync.aligned.m8n8.x4.shared.b16 {%0,%1,%2,%3}, [%4];"
                 : "=r"(r0), "=r"(r1), "=r"(r2), "=r"(r3) : "r"(a));
}
__device__ __forceinline__ void lds128(unsigned& r0, unsigned& r1, unsigned& r2, unsigned& r3,
                                       uint32_t a) {
    asm volatile("ld.shared.v4.b32 {%0,%1,%2,%3}, [%4];"
                 : "=r"(r0), "=r"(r1), "=r"(r2), "=r"(r3) : "r"(a));
}

// w2 ternarize slice: covers float4 range [sid*1024, sid*1024+1024)
__device__ __forceinline__ void w2_slice(const float4* __restrict__ w2v, int sid, int tid) {
    size_t base = (size_t)sid * 1024;
    #pragma unroll
    for (int j = 0; j < 4; j++) {
        size_t i = base + tid + j * 256;
        int e = (int)(i >> 20);                 // 1048576 float4 per expert
        float sc = 1.0f / g_mval[10 + e];
        float4 v = w2v[i];
        char4 c;
        c.x = terq(v.x * sc); c.y = terq(v.y * sc);
        c.z = terq(v.z * sc); c.w = terq(v.w * sc);
        ((char4*)g_wq2)[i] = c;
    }
}

// ---------------- 1) weight stats: per-tensor sum |w| ----------------
__global__ void stats_partial(const float* __restrict__ wr, const float* __restrict__ wn,
                              const float* __restrict__ w1, const float* __restrict__ w2) {
    int slot = blockIdx.y, chunk = blockIdx.x;
    const float4* p;
    int nvec;
    if (slot < 2) {
        if (chunk != 0) return;
        p = (const float4*)(slot ? wn : wr);
        nvec = NEXP * DIMX / 4;
    } else if (slot < 10) {
        p = (const float4*)(w1 + (size_t)(slot - 2) * HIDX * DIMX) + (size_t)chunk * 8192;
        nvec = 8192;
    } else {
        p = (const float4*)(w2 + (size_t)(slot - 10) * DIMX * HIDX) + (size_t)chunk * 8192;
        nvec = 8192;
    }
    float s = 0.f;
    for (int i = threadIdx.x; i < nvec; i += 256) {
        float4 v = p[i];
        s += fabsf(v.x) + fabsf(v.y) + fabsf(v.z) + fabsf(v.w);
    }
    __shared__ float sh[8];
    #pragma unroll
    for (int o = 16; o; o >>= 1) s += __shfl_xor_sync(0xffffffffu, s, o);
    if ((threadIdx.x & 31) == 0) sh[threadIdx.x >> 5] = s;
    __syncthreads();
    if (threadIdx.x == 0) {
        float t = 0.f;
        #pragma unroll
        for (int j = 0; j < 8; j++) t += sh[j];
        g_partial[slot * 128 + chunk] = t;
    }
}

// ---------------- 2) finalize: mvals + small-weight ternarize + zero counters ----------------
__global__ void finalize(const float* __restrict__ wr, const float* __restrict__ wn) {
    int tid = threadIdx.x;
    __shared__ float sm[18];
    if (tid < 18) {
        int nc = (tid < 2) ? 1 : 128;
        float sum = 0.f;
        for (int c = 0; c < nc; c++) sum += g_partial[tid * 128 + c];
        float nelem = (tid < 2) ? (float)(NEXP * DIMX) : (float)((size_t)HIDX * DIMX);
        float m = fmaxf(sum / nelem, 1e-5f);
        g_mval[tid] = m;
        sm[tid] = m;
    }
    if (tid < NEXP) g_cnt[tid] = 0;
    __syncthreads();
    float sc0 = 1.0f / sm[0], sc1 = 1.0f / sm[1];
    for (int i = tid; i < NEXP * DIMX; i += 256) {
        g_wqr[i] = terq(wr[i] * sc0);
        g_wqn[i] = terq(wn[i] * sc1);
    }
}

// ---------------- 3) mega: w1 ternarize (z=0) + act-quant+router (z=1) ----------------
__global__ __launch_bounds__(256) void mega(const float* __restrict__ w1,
                                            const float* __restrict__ x,
                                            const float* __restrict__ eps) {
    int z = blockIdx.z;
    int tid = threadIdx.x;
    if (z == 0) {
        size_t i = (size_t)blockIdx.x * 256 + tid;   // float4 index, exactly covers w1
        int e = (int)(i >> 20);
        float sc = 1.0f / g_mval[2 + e];
        float4 v = ((const float4*)w1)[i];
        char4 c;
        c.x = terq(v.x * sc); c.y = terq(v.y * sc); c.z = terq(v.z * sc); c.w = terq(v.w * sc);
        ((char4*)g_wq1)[i] = c;
        return;
    }
    int t = blockIdx.x;
    if (t >= TTOK) return;

    __shared__ float shs[8], shm[8], svals[8], sdq[1];
    __shared__ int sx[256];

    float4 v = ((const float4*)(x + (size_t)t * DIMX))[tid];
    float ss = v.x * v.x + v.y * v.y + v.z * v.z + v.w * v.w;
    float am = fmaxf(fmaxf(fabsf(v.x), fabsf(v.y)), fmaxf(fabsf(v.z), fabsf(v.w)));
    #pragma unroll
    for (int o = 16; o; o >>= 1) {
        ss += __shfl_xor_sync(0xffffffffu, ss, o);
        am = fmaxf(am, __shfl_xor_sync(0xffffffffu, am, o));
    }
    if ((tid & 31) == 0) { shs[tid >> 5] = ss; shm[tid >> 5] = am; }
    __syncthreads();
    float tss = 0.f, tam = 0.f;
    #pragma unroll
    for (int j = 0; j < 8; j++) { tss += shs[j]; tam = fmaxf(tam, shm[j]); }
    float rs = rsqrtf(tss / (float)DIMX + 1e-6f);
    float a = fmaxf(tam * rs, 1e-5f);
    float sc = 127.0f / a;
    if (tid == 0) { g_deqx[t] = a / 127.0f; sdq[0] = a / 127.0f; }
    char4 c;
    c.x = qi8(v.x * rs * sc); c.y = qi8(v.y * rs * sc);
    c.z = qi8(v.z * rs * sc); c.w = qi8(v.w * rs * sc);
    ((char4*)(g_xq + (size_t)t * DIMX))[tid] = c;
    int ci;
    memcpy(&ci, &c, 4);
    sx[tid] = ci;
    __syncthreads();

    // router: warp w handles expert w
    int w = tid >> 5, lane = tid & 31;
    const int* wrp = (const int*)(g_wqr + w * DIMX);
    const int* wnp = (const int*)(g_wqn + w * DIMX);
    int ar = 0, an = 0;
    #pragma unroll
    for (int j = 0; j < 8; j++) {
        int xi = sx[lane + 32 * j];
        ar = __dp4a(xi, wrp[lane + 32 * j], ar);
        an = __dp4a(xi, wnp[lane + 32 * j], an);
    }
    #pragma unroll
    for (int o = 16; o; o >>= 1) {
        ar += __shfl_xor_sync(0xffffffffu, ar, o);
        an += __shfl_xor_sync(0xffffffffu, an, o);
    }
    if (lane == 0) {
        float dq = sdq[0];
        float lg = (float)ar * dq * g_mval[0];
        float nl = (float)an * dq * g_mval[1];
        float sp = fmaxf(nl, 0.f) + log1pf(expf(-fabsf(nl)));
        svals[w] = lg + eps[t * NEXP + w] * sp;
    }
    __syncthreads();
    if (tid == 0) {
        float v0 = -1e30f, v1 = -1e30f;
        int i0 = 0, i1 = 0;
        #pragma unroll
        for (int e = 0; e < NEXP; e++) {
            float vv = svals[e];
            if (vv > v0) { v1 = v0; i1 = i0; v0 = vv; i0 = e; }
            else if (vv > v1) { v1 = vv; i1 = e; }
        }
        float ex = expf(v1 - v0);
        float inv = 1.0f / (1.0f + ex);
        int p0 = atomicAdd(&g_cnt[i0], 1);
        g_tok[i0 * TTOK + p0] = t;
        int p1 = atomicAdd(&g_cnt[i1], 1);
        g_tok[i1 * TTOK + p1] = t;
        g_tpe[t * 2]     = (i0 << 16) | p0;
        g_tpe[t * 2 + 1] = (i1 << 16) | p1;
        g_tg[t * 2]      = inv;
        g_tg[t * 2 + 1]  = ex * inv;
    }
}

// ---------------- 4/6) HYBRID tensor+dp4a int8 grouped GEMM ----------------
// Tile 128x128: cols 0..95 via mma.sync (tensor pipe), cols 96..127 via dp4a
// (fma pipe) from the same smem stages; dp4a uses 32-bit asm smem loads and a
// non-unrolled kq loop to keep regs <= 85 so launch_bounds(256,3) holds
// 3 blocks/SM (the R14 hybrid lost its gemm1 gain to 128-reg / 2-block occ).
// MODE 2 uses a deterministic K-split into int32 partial buffers.
#define BM 128
#define BN 128
#define BKK 64
#define LDSS 80          // 64 + 16 pad
#define STG_STRIDE (2 * BM * LDSS)   // A stage + B stage = 20480
#define GSMEM (3 * STG_STRIDE)       // 3 stages = 61440 B

__device__ __forceinline__ void mma8(int (&c)[4], const unsigned (&a)[4], const unsigned (&b)[2]) {
    asm volatile(
        "mma.sync.aligned.m16n8k32.row.col.s32.s8.s8.s32 "
        "{%0,%1,%2,%3}, {%4,%5,%6,%7}, {%8,%9}, {%0,%1,%2,%3};\n"
        : "+r"(c[0]), "+r"(c[1]), "+r"(c[2]), "+r"(c[3])
        : "r"(a[0]), "r"(a[1]), "r"(a[2]), "r"(a[3]), "r"(b[0]), "r"(b[1]));
}

template <int MODE>
__global__ __launch_bounds__(256, 3) void bit_gemm(const float* __restrict__ w2fp) {
    constexpr int K = (MODE == 1) ? DIMX : HIDX;          // full row stride
    constexpr int KRUN = (MODE == 1) ? DIMX : HIDX / 2;   // K covered per block
    constexpr int N = (MODE == 1) ? HIDX : DIMX;
    constexpr int NITER = KRUN / BKK;
    const int e = (MODE == 1) ? blockIdx.z : (blockIdx.z & 7);
    const int ksp = (MODE == 1) ? 0 : (blockIdx.z >> 3);
    const int kbase = ksp * KRUN;
    const int cnt = g_cnt[e];
    const int m0 = blockIdx.y * BM;
    const int tid = threadIdx.x;
    if (m0 >= cnt) {
        if (MODE == 1) {
            int bid = blockIdx.x + (int)gridDim.x * (blockIdx.y + (int)gridDim.y * blockIdx.z);
            w2_slice((const float4*)w2fp, bid, tid);
        }
        return;
    }
    const int n0 = blockIdx.x * BN;
    int off = 0;
    #pragma unroll
    for (int j = 0; j < NEXP; j++) if (j < e) off += g_cnt[j];

    extern __shared__ char dsm[];
    const uint32_t smb = s2u(dsm);

    const int lane = tid & 31, warp = tid >> 5;
    const int wm = warp >> 2, wn = warp & 3;   // 2x4 warp grid

    // tensor: warp tile 64 rows x 24 cols (cols wn*24 .. +24)
    int acc[4][3][4];
    #pragma unroll
    for (int a = 0; a < 4; a++)
        #pragma unroll
        for (int b = 0; b < 3; b++)
            #pragma unroll
            for (int c = 0; c < 4; c++) acc[a][b][c] = 0;
    // dp4a: warp handles rows wm*64..+64 (2 per lane), cols 96 + wn*8 .. +8
    int dacc[2][8];
    #pragma unroll
    for (int a = 0; a < 2; a++)
        #pragma unroll
        for (int b = 0; b < 8; b++) dacc[a][b] = 0;

    const int lr = tid >> 1;            // staged row (0..127)
    const int lcb = (tid & 1) * 32;     // byte offset within 64B k-chunk
    const bool aok = (m0 + lr) < cnt;
    const signed char* Ap;
    if (MODE == 1) {
        int tok = aok ? g_tok[e * TTOK + m0 + lr] : 0;
        Ap = g_xq + (size_t)tok * K + kbase + lcb;
    } else {
        int r = aok ? (off + m0 + lr) : 0;
        Ap = g_hq + (size_t)r * K + kbase + lcb;
    }
    const unsigned aSz = aok ? 16u : 0u;
    const signed char* wsrc = (MODE == 1) ? g_wq1 : g_wq2;
    const signed char* Bp = wsrc + (size_t)e * N * K + (size_t)(n0 + lr) * K + kbase + lcb;

    const uint32_t cpOff = (uint32_t)(lr * LDSS + lcb);
    const uint32_t aLO = (uint32_t)((lane & 15) * LDSS + (lane >> 4) * 16);
    const uint32_t bLO = (uint32_t)(((lane >> 4) * 8 + (lane & 7)) * LDSS + ((lane >> 3) & 1) * 16);
    // dp4a 32-bit smem address offsets (within a stage)
    const uint32_t dA0 = (uint32_t)((wm * 64 + lane) * LDSS);
    const uint32_t dA1 = (uint32_t)((wm * 64 + 32 + lane) * LDSS);
    const uint32_t dB0 = (uint32_t)(BM * LDSS + (96 + wn * 8) * LDSS);

    auto prefetch = [&](int it) {
        int s = it;
        while (s >= 3) s -= 3;
        uint32_t ab = smb + s * STG_STRIDE + cpOff;
        uint32_t bb = ab + BM * LDSS;
        const signed char* as = Ap;
        const signed char* bs = Bp;
        unsigned asz = 0, bsz = 0;
        if (it < NITER) {
            as = Ap + it * BKK;
            bs = Bp + it * BKK;
            asz = aSz;
            bsz = 16;
        }
        asm volatile("cp.async.cg.shared.global [%0], [%1], 16, %2;"
                     :: "r"(ab), "l"(as), "r"(asz) : "memory");
        asm volatile("cp.async.cg.shared.global [%0], [%1], 16, %2;"
                     :: "r"(ab + 16), "l"(as + 16), "r"(asz) : "memory");
        asm volatile("cp.async.cg.shared.global [%0], [%1], 16, %2;"
                     :: "r"(bb), "l"(bs), "r"(bsz) : "memory");
        asm volatile("cp.async.cg.shared.global [%0], [%1], 16, %2;"
                     :: "r"(bb + 16), "l"(bs + 16), "r"(bsz) : "memory");
        asm volatile("cp.async.commit_group;" ::: "memory");
    };

    prefetch(0);
    prefetch(1);
    #pragma unroll 1
    for (int i = 0; i < NITER; i++) {
        prefetch(i + 2);
        asm volatile("cp.async.wait_group 2;" ::: "memory");   // my group-i copies landed
        __syncthreads();                                       // everyone's group-i copies landed
        int s = i;
        while (s >= 3) s -= 3;
        const uint32_t stB = smb + s * STG_STRIDE;
        const uint32_t aB = stB;
        const uint32_t bB = stB + BM * LDSS;

        // tensor part: cols 0..95
        #pragma unroll
        for (int ks = 0; ks < 2; ks++) {
            unsigned af[4][4];
            #pragma unroll
            for (int mi = 0; mi < 4; mi++)
                ldsm4(af[mi][0], af[mi][1], af[mi][2], af[mi][3],
                      aB + (uint32_t)((wm * 64 + mi * 16) * LDSS + ks * 32) + aLO);
            unsigned bf[4][2];
            #pragma unroll
            for (int np = 0; np < 2; np++)
                ldsm4(bf[np * 2][0], bf[np * 2][1], bf[np * 2 + 1][0], bf[np * 2 + 1][1],
                      bB + (uint32_t)((wn * 24 + np * 16) * LDSS + ks * 32) + bLO);
            #pragma unroll
            for (int mi = 0; mi < 4; mi++)
                #pragma unroll
                for (int ni = 0; ni < 3; ni++) mma8(acc[mi][ni], af[mi], bf[ni]);
        }

        // dp4a part: cols 96..127 (fma pipe, concurrent with tensor pipe)
        #pragma unroll 1
        for (int kq = 0; kq < 4; kq++) {
            unsigned a0[4], a1[4];
            lds128(a0[0], a0[1], a0[2], a0[3], stB + dA0 + kq * 16);
            lds128(a1[0], a1[1], a1[2], a1[3], stB + dA1 + kq * 16);
            #pragma unroll
            for (int c = 0; c < 8; c++) {
                unsigned bv[4];
                lds128(bv[0], bv[1], bv[2], bv[3], stB + dB0 + (uint32_t)(c * LDSS) + kq * 16);
                int t0 = dacc[0][c], t1 = dacc[1][c];
                t0 = __dp4a((int)a0[0], (int)bv[0], t0); t1 = __dp4a((int)a1[0], (int)bv[0], t1);
                t0 = __dp4a((int)a0[1], (int)bv[1], t0); t1 = __dp4a((int)a1[1], (int)bv[1], t1);
                t0 = __dp4a((int)a0[2], (int)bv[2], t0); t1 = __dp4a((int)a1[2], (int)bv[2], t1);
                t0 = __dp4a((int)a0[3], (int)bv[3], t0); t1 = __dp4a((int)a1[3], (int)bv[3], t1);
                dacc[0][c] = t0; dacc[1][c] = t1;
            }
        }
        __syncthreads();                                       // release stage i for reuse
    }

    if (MODE == 1) {
        const float m1 = g_mval[2 + e];
        // tensor epilogue: cols 0..95
        #pragma unroll
        for (int mi = 0; mi < 4; mi++) {
            #pragma unroll
            for (int half = 0; half < 2; half++) {
                int rrow = wm * 64 + mi * 16 + (lane >> 2) + half * 8;
                int pos = m0 + rrow;
                if (pos < cnt) {
                    float d = g_deqx[g_tok[e * TTOK + pos]] * m1;
                    float* hrow = g_h + (size_t)(off + pos) * HIDX + n0;
                    #pragma unroll
                    for (int ni = 0; ni < 3; ni++) {
                        int col = wn * 24 + ni * 8 + (lane & 3) * 2;
                        float2 v;
                        v.x = fmaxf(0.f, (float)acc[mi][ni][half * 2 + 0] * d);
                        v.y = fmaxf(0.f, (float)acc[mi][ni][half * 2 + 1] * d);
                        *(float2*)(hrow + col) = v;
                    }
                }
            }
        }
        // dp4a epilogue: cols 96..127
        #pragma unroll
        for (int rr = 0; rr < 2; rr++) {
            int pos = m0 + wm * 64 + rr * 32 + lane;
            if (pos < cnt) {
                float d = g_deqx[g_tok[e * TTOK + pos]] * m1;
                float* hrow = g_h + (size_t)(off + pos) * HIDX + n0 + 96 + wn * 8;
                float4 v0, v1;
                v0.x = fmaxf(0.f, (float)dacc[rr][0] * d);
                v0.y = fmaxf(0.f, (float)dacc[rr][1] * d);
                v0.z = fmaxf(0.f, (float)dacc[rr][2] * d);
                v0.w = fmaxf(0.f, (float)dacc[rr][3] * d);
                v1.x = fmaxf(0.f, (float)dacc[rr][4] * d);
                v1.y = fmaxf(0.f, (float)dacc[rr][5] * d);
                v1.z = fmaxf(0.f, (float)dacc[rr][6] * d);
                v1.w = fmaxf(0.f, (float)dacc[rr][7] * d);
                *(float4*)(hrow) = v0;
                *(float4*)(hrow + 4) = v1;
            }
        }
        // this block's w2 ternarize slice (overlaps with other blocks' MMA work)
        int bid = blockIdx.x + (int)gridDim.x * (blockIdx.y + (int)gridDim.y * blockIdx.z);
        w2_slice((const float4*)w2fp, bid, tid);
    } else {
        int* yp = ksp ? g_yp1 : g_yp0;
        #pragma unroll
        for (int mi = 0; mi < 4; mi++) {
            #pragma unroll
            for (int half = 0; half < 2; half++) {
                int rrow = wm * 64 + mi * 16 + (lane >> 2) + half * 8;
                int pos = m0 + rrow;
                if (pos < cnt) {
                    int* yrow = yp + (size_t)(off + pos) * DIMX + n0;
                    #pragma unroll
                    for (int ni = 0; ni < 3; ni++) {
                        int col = wn * 24 + ni * 8 + (lane & 3) * 2;
                        int2 v;
                        v.x = acc[mi][ni][half * 2 + 0];
                        v.y = acc[mi][ni][half * 2 + 1];
                        *(int2*)(yrow + col) = v;
                    }
                }
            }
        }
        #pragma unroll
        for (int rr = 0; rr < 2; rr++) {
            int pos = m0 + wm * 64 + rr * 32 + lane;
            if (pos < cnt) {
                int* yrow = yp + (size_t)(off + pos) * DIMX + n0 + 96 + wn * 8;
                int4 v0, v1;
                v0.x = dacc[rr][0]; v0.y = dacc[rr][1]; v0.z = dacc[rr][2]; v0.w = dacc[rr][3];
                v1.x = dacc[rr][4]; v1.y = dacc[rr][5]; v1.z = dacc[rr][6]; v1.w = dacc[rr][7];
                *(int4*)(yrow) = v0;
                *(int4*)(yrow + 4) = v1;
            }
        }
    }
}

// ---------------- 5) hidden quant: one block per packed row ----------------
__global__ void h_quant() {
    size_t row = blockIdx.x;   // 0 .. 2*TTOK-1 (all slots always filled)
    const float4* hp = (const float4*)(g_h + row * HIDX);
    int tid = threadIdx.x;
    float4 r[4];
    float ss = 0.f, am = 0.f;
    #pragma unroll
    for (int j = 0; j < 4; j++) {
        r[j] = hp[tid + 256 * j];
        ss += r[j].x * r[j].x + r[j].y * r[j].y + r[j].z * r[j].z + r[j].w * r[j].w;
        am = fmaxf(am, fmaxf(fmaxf(fabsf(r[j].x), fabsf(r[j].y)), fmaxf(fabsf(r[j].z), fabsf(r[j].w))));
    }
    __shared__ float shs[8], shm[8];
    #pragma unroll
    for (int o = 16; o; o >>= 1) {
        ss += __shfl_xor_sync(0xffffffffu, ss, o);
        am = fmaxf(am, __shfl_xor_sync(0xffffffffu, am, o));
    }
    if ((tid & 31) == 0) { shs[tid >> 5] = ss; shm[tid >> 5] = am; }
    __syncthreads();
    float tss = 0.f, tam = 0.f;
    #pragma unroll
    for (int j = 0; j < 8; j++) { tss += shs[j]; tam = fmaxf(tam, shm[j]); }
    float rs = rsqrtf(tss / (float)HIDX + 1e-6f);
    float a = fmaxf(tam * rs, 1e-5f);
    float sc = 127.0f / a;
    if (tid == 0) g_deqh[row] = a / 127.0f;
    char4* dst = (char4*)(g_hq + row * HIDX);
    #pragma unroll
    for (int j = 0; j < 4; j++) {
        char4 c;
        c.x = qi8(r[j].x * rs * sc); c.y = qi8(r[j].y * rs * sc);
        c.z = qi8(r[j].z * rs * sc); c.w = qi8(r[j].w * rs * sc);
        dst[tid + 256 * j] = c;
    }
}

// ---------------- 7) gated combine (deterministic, atomic-free) ----------------
__global__ void combine(float* __restrict__ out) {
    __shared__ int soff[NEXP];
    int t = blockIdx.x, i = threadIdx.x;
    if (i == 0) {
        int o = 0;
        #pragma unroll
        for (int j = 0; j < NEXP; j++) { soff[j] = o; o += g_cnt[j]; }
    }
    __syncthreads();
    int a0 = g_tpe[t * 2], a1 = g_tpe[t * 2 + 1];
    int e0 = a0 >> 16, e1 = a1 >> 16;
    int row0 = soff[e0] + (a0 & 0xFFFF);
    int row1 = soff[e1] + (a1 & 0xFFFF);
    float d0 = g_deqh[row0] * g_mval[10 + e0] * g_tg[t * 2];
    float d1 = g_deqh[row1] * g_mval[10 + e1] * g_tg[t * 2 + 1];
    size_t r0 = (size_t)row0 * DIMX;
    size_t r1 = (size_t)row1 * DIMX;
    int4 p00 = ((const int4*)(g_yp0 + r0))[i];
    int4 p01 = ((const int4*)(g_yp1 + r0))[i];
    int4 p10 = ((const int4*)(g_yp0 + r1))[i];
    int4 p11 = ((const int4*)(g_yp1 + r1))[i];
    float4 o;
    o.x = (float)(p00.x + p01.x) * d0 + (float)(p10.x + p11.x) * d1;
    o.y = (float)(p00.y + p01.y) * d0 + (float)(p10.y + p11.y) * d1;
    o.z = (float)(p00.z + p01.z) * d0 + (float)(p10.z + p11.z) * d1;
    o.w = (float)(p00.w + p01.w) * d0 + (float)(p10.w + p11.w) * d1;
    ((float4*)(out + (size_t)t * DIMX))[i] = o;
}

// ---------------- launch ----------------
extern "C" void kernel_launch(void* const* d_in, const int* in_sizes, int n_in,
                              void* d_out, int out_size) {
    const float* x   = (const float*)d_in[0];
    const float* eps = (const float*)d_in[1];
    const float* wr  = (const float*)d_in[2];
    const float* wn  = (const float*)d_in[3];
    const float* w1  = (const float*)d_in[4];
    const float* w2  = (const float*)d_in[5];
    float* out = (float*)d_out;

    cudaFuncSetAttribute(bit_gemm<1>, cudaFuncAttributeMaxDynamicSharedMemorySize, GSMEM);
    cudaFuncSetAttribute(bit_gemm<2>, cudaFuncAttributeMaxDynamicSharedMemorySize, GSMEM);

    stats_partial<<<dim3(128, 18), 256>>>(wr, wn, w1, w2);      // 1
    finalize<<<1, 256>>>(wr, wn);                               // 2
    mega<<<dim3(32768, 1, 2), 256>>>(w1, x, eps);               // 3
    bit_gemm<1><<<dim3(HIDX / BN, TTOK / BM, NEXP), 256, GSMEM>>>(w2);   // 4 <- profiled (hybrid, 3 blk/SM)
    h_quant<<<2 * TTOK, 256>>>();                               // 5
    bit_gemm<2><<<dim3(DIMX / BN, TTOK / BM, NEXP * 2), 256, GSMEM>>>(nullptr);  // 6 (K-split)
    combine<<<TTOK, 256>>>(out);                                // 7
}

// round 16
// speedup vs baseline: 1.2246x; 1.0199x over previous
#include <cuda_runtime.h>
#include <cstdint>

#define DIMX 1024
#define NEXP 8
#define HIDX 4096
#define TTOK 4096   // B*S = 2*2048
#define KSPL 4      // gemm2 K-split factor

// ---------------- static scratch (no allocations allowed) ----------------
__device__ signed char g_wq1[(size_t)NEXP * HIDX * DIMX];   // ternary w1
__device__ signed char g_wq2[(size_t)NEXP * DIMX * HIDX];   // ternary w2
__device__ signed char g_wqr[NEXP * DIMX];
__device__ signed char g_wqn[NEXP * DIMX];
__device__ float g_partial[18 * 128];
__device__ float g_mval[18];
__device__ signed char g_xq[(size_t)TTOK * DIMX];
__device__ float g_deqx[TTOK];
__device__ int   g_cnt[NEXP];
__device__ int   g_tok[NEXP * TTOK];
__device__ int   g_tpe[TTOK * 2];    // (expert<<16)|pos per token slot
__device__ float g_tg[TTOK * 2];     // gates per token slot
__device__ float g_h[(size_t)2 * TTOK * HIDX];               // fp32 hidden
__device__ signed char g_hq[(size_t)2 * TTOK * HIDX];        // int8 hidden
__device__ float g_deqh[2 * TTOK];
__device__ int g_yp[(size_t)KSPL * 2 * TTOK * DIMX];         // int32 partials (4 K-quarters)

// ---------------- helpers ----------------
__device__ __forceinline__ signed char terq(float x) {
    float r = rintf(x);
    r = fminf(1.f, fmaxf(-1.f, r));
    return (signed char)(int)r;
}
__device__ __forceinline__ signed char qi8(float x) {
    float r = rintf(x);
    r = fminf(127.f, fmaxf(-128.f, r));
    return (signed char)(int)r;
}
__device__ __forceinline__ uint32_t s2u(const void* p) {
    uint32_t a;
    asm("{ .reg .u64 t; cvta.to.shared.u64 t, %1; cvt.u32.u64 %0, t; }" : "=r"(a) : "l"(p));
    return a;
}
__device__ __forceinline__ void ldsm4(unsigned& r0, unsigned& r1, unsigned& r2, unsigned& r3,
                                      uint32_t a) {
    asm volatile("ldmatrix.sync.aligned.m8n8.x4.shared.b16 {%0,%1,%2,%3}, [%4];"
                 : "=r"(r0), "=r"(r1), "=r"(r2), "=r"(r3) : "r"(a));
}
__device__ __forceinline__ void lds128(unsigned& r0, unsigned& r1, unsigned& r2, unsigned& r3,
                                       uint32_t a) {
    asm volatile("ld.shared.v4.b32 {%0,%1,%2,%3}, [%4];"
                 : "=r"(r0), "=r"(r1), "=r"(r2), "=r"(r3) : "r"(a));
}

// w2 ternarize slice: covers float4 range [sid*1024, sid*1024+1024)
__device__ __forceinline__ void w2_slice(const float4* __restrict__ w2v, int sid, int tid) {
    size_t base = (size_t)sid * 1024;
    #pragma unroll
    for (int j = 0; j < 4; j++) {
        size_t i = base + tid + j * 256;
        int e = (int)(i >> 20);                 // 1048576 float4 per expert
        float sc = 1.0f / g_mval[10 + e];
        float4 v = w2v[i];
        char4 c;
        c.x = terq(v.x * sc); c.y = terq(v.y * sc);
        c.z = terq(v.z * sc); c.w = terq(v.w * sc);
        ((char4*)g_wq2)[i] = c;
    }
}

// ---------------- 1) weight stats: per-tensor sum |w| ----------------
__global__ void stats_partial(const float* __restrict__ wr, const float* __restrict__ wn,
                              const float* __restrict__ w1, const float* __restrict__ w2) {
    int slot = blockIdx.y, chunk = blockIdx.x;
    const float4* p;
    int nvec;
    if (slot < 2) {
        if (chunk != 0) return;
        p = (const float4*)(slot ? wn : wr);
        nvec = NEXP * DIMX / 4;
    } else if (slot < 10) {
        p = (const float4*)(w1 + (size_t)(slot - 2) * HIDX * DIMX) + (size_t)chunk * 8192;
        nvec = 8192;
    } else {
        p = (const float4*)(w2 + (size_t)(slot - 10) * DIMX * HIDX) + (size_t)chunk * 8192;
        nvec = 8192;
    }
    float s = 0.f;
    for (int i = threadIdx.x; i < nvec; i += 256) {
        float4 v = p[i];
        s += fabsf(v.x) + fabsf(v.y) + fabsf(v.z) + fabsf(v.w);
    }
    __shared__ float sh[8];
    #pragma unroll
    for (int o = 16; o; o >>= 1) s += __shfl_xor_sync(0xffffffffu, s, o);
    if ((threadIdx.x & 31) == 0) sh[threadIdx.x >> 5] = s;
    __syncthreads();
    if (threadIdx.x == 0) {
        float t = 0.f;
        #pragma unroll
        for (int j = 0; j < 8; j++) t += sh[j];
        g_partial[slot * 128 + chunk] = t;
    }
}

// ---------------- 2) finalize: mvals + small-weight ternarize + zero counters ----------------
__global__ void finalize(const float* __restrict__ wr, const float* __restrict__ wn) {
    int tid = threadIdx.x;
    __shared__ float sm[18];
    if (tid < 18) {
        int nc = (tid < 2) ? 1 : 128;
        float sum = 0.f;
        for (int c = 0; c < nc; c++) sum += g_partial[tid * 128 + c];
        float nelem = (tid < 2) ? (float)(NEXP * DIMX) : (float)((size_t)HIDX * DIMX);
        float m = fmaxf(sum / nelem, 1e-5f);
        g_mval[tid] = m;
        sm[tid] = m;
    }
    if (tid < NEXP) g_cnt[tid] = 0;
    __syncthreads();
    float sc0 = 1.0f / sm[0], sc1 = 1.0f / sm[1];
    for (int i = tid; i < NEXP * DIMX; i += 256) {
        g_wqr[i] = terq(wr[i] * sc0);
        g_wqn[i] = terq(wn[i] * sc1);
    }
}

// ---------------- 3) mega: w1 ternarize (z=0) + act-quant+router (z=1) ----------------
__global__ __launch_bounds__(256) void mega(const float* __restrict__ w1,
                                            const float* __restrict__ x,
                                            const float* __restrict__ eps) {
    int z = blockIdx.z;
    int tid = threadIdx.x;
    if (z == 0) {
        size_t i = (size_t)blockIdx.x * 256 + tid;   // float4 index, exactly covers w1
        int e = (int)(i >> 20);
        float sc = 1.0f / g_mval[2 + e];
        float4 v = ((const float4*)w1)[i];
        char4 c;
        c.x = terq(v.x * sc); c.y = terq(v.y * sc); c.z = terq(v.z * sc); c.w = terq(v.w * sc);
        ((char4*)g_wq1)[i] = c;
        return;
    }
    int t = blockIdx.x;
    if (t >= TTOK) return;

    __shared__ float shs[8], shm[8], svals[8], sdq[1];
    __shared__ int sx[256];

    float4 v = ((const float4*)(x + (size_t)t * DIMX))[tid];
    float ss = v.x * v.x + v.y * v.y + v.z * v.z + v.w * v.w;
    float am = fmaxf(fmaxf(fabsf(v.x), fabsf(v.y)), fmaxf(fabsf(v.z), fabsf(v.w)));
    #pragma unroll
    for (int o = 16; o; o >>= 1) {
        ss += __shfl_xor_sync(0xffffffffu, ss, o);
        am = fmaxf(am, __shfl_xor_sync(0xffffffffu, am, o));
    }
    if ((tid & 31) == 0) { shs[tid >> 5] = ss; shm[tid >> 5] = am; }
    __syncthreads();
    float tss = 0.f, tam = 0.f;
    #pragma unroll
    for (int j = 0; j < 8; j++) { tss += shs[j]; tam = fmaxf(tam, shm[j]); }
    float rs = rsqrtf(tss / (float)DIMX + 1e-6f);
    float a = fmaxf(tam * rs, 1e-5f);
    float sc = 127.0f / a;
    if (tid == 0) { g_deqx[t] = a / 127.0f; sdq[0] = a / 127.0f; }
    char4 c;
    c.x = qi8(v.x * rs * sc); c.y = qi8(v.y * rs * sc);
    c.z = qi8(v.z * rs * sc); c.w = qi8(v.w * rs * sc);
    ((char4*)(g_xq + (size_t)t * DIMX))[tid] = c;
    int ci;
    memcpy(&ci, &c, 4);
    sx[tid] = ci;
    __syncthreads();

    // router: warp w handles expert w
    int w = tid >> 5, lane = tid & 31;
    const int* wrp = (const int*)(g_wqr + w * DIMX);
    const int* wnp = (const int*)(g_wqn + w * DIMX);
    int ar = 0, an = 0;
    #pragma unroll
    for (int j = 0; j < 8; j++) {
        int xi = sx[lane + 32 * j];
        ar = __dp4a(xi, wrp[lane + 32 * j], ar);
        an = __dp4a(xi, wnp[lane + 32 * j], an);
    }
    #pragma unroll
    for (int o = 16; o; o >>= 1) {
        ar += __shfl_xor_sync(0xffffffffu, ar, o);
        an += __shfl_xor_sync(0xffffffffu, an, o);
    }
    if (lane == 0) {
        float dq = sdq[0];
        float lg = (float)ar * dq * g_mval[0];
        float nl = (float)an * dq * g_mval[1];
        float sp = fmaxf(nl, 0.f) + log1pf(expf(-fabsf(nl)));
        svals[w] = lg + eps[t * NEXP + w] * sp;
    }
    __syncthreads();
    if (tid == 0) {
        float v0 = -1e30f, v1 = -1e30f;
        int i0 = 0, i1 = 0;
        #pragma unroll
        for (int e = 0; e < NEXP; e++) {
            float vv = svals[e];
            if (vv > v0) { v1 = v0; i1 = i0; v0 = vv; i0 = e; }
            else if (vv > v1) { v1 = vv; i1 = e; }
        }
        float ex = expf(v1 - v0);
        float inv = 1.0f / (1.0f + ex);
        int p0 = atomicAdd(&g_cnt[i0], 1);
        g_tok[i0 * TTOK + p0] = t;
        int p1 = atomicAdd(&g_cnt[i1], 1);
        g_tok[i1 * TTOK + p1] = t;
        g_tpe[t * 2]     = (i0 << 16) | p0;
        g_tpe[t * 2 + 1] = (i1 << 16) | p1;
        g_tg[t * 2]      = inv;
        g_tg[t * 2 + 1]  = ex * inv;
    }
}

// ---------------- 4/6) HYBRID tensor+dp4a int8 grouped GEMM ----------------
// Tile 128x128: cols 0..95 via mma.sync (tensor pipe), cols 96..127 via dp4a
// (fma pipe) from the same smem stages; 32-bit asm smem loads + non-unrolled
// kq loop keep regs <= 85 so launch_bounds(256,3) holds 3 blocks/SM.
// MODE 2 uses a deterministic 4-way K-split into int32 partial buffers
// (doubles live tiles vs 2-way: 2.3 -> 4.6 waves, kills the wave tail).
#define BM 128
#define BN 128
#define BKK 64
#define LDSS 80          // 64 + 16 pad
#define STG_STRIDE (2 * BM * LDSS)   // A stage + B stage = 20480
#define GSMEM (3 * STG_STRIDE)       // 3 stages = 61440 B

__device__ __forceinline__ void mma8(int (&c)[4], const unsigned (&a)[4], const unsigned (&b)[2]) {
    asm volatile(
        "mma.sync.aligned.m16n8k32.row.col.s32.s8.s8.s32 "
        "{%0,%1,%2,%3}, {%4,%5,%6,%7}, {%8,%9}, {%0,%1,%2,%3};\n"
        : "+r"(c[0]), "+r"(c[1]), "+r"(c[2]), "+r"(c[3])
        : "r"(a[0]), "r"(a[1]), "r"(a[2]), "r"(a[3]), "r"(b[0]), "r"(b[1]));
}

template <int MODE>
__global__ __launch_bounds__(256, 3) void bit_gemm(const float* __restrict__ w2fp) {
    constexpr int K = (MODE == 1) ? DIMX : HIDX;             // full row stride
    constexpr int KRUN = (MODE == 1) ? DIMX : HIDX / KSPL;   // K covered per block
    constexpr int N = (MODE == 1) ? HIDX : DIMX;
    constexpr int NITER = KRUN / BKK;
    const int e = (MODE == 1) ? blockIdx.z : (blockIdx.z & 7);
    const int ksp = (MODE == 1) ? 0 : (blockIdx.z >> 3);
    const int kbase = ksp * KRUN;
    const int cnt = g_cnt[e];
    const int m0 = blockIdx.y * BM;
    const int tid = threadIdx.x;
    if (m0 >= cnt) {
        if (MODE == 1) {
            int bid = blockIdx.x + (int)gridDim.x * (blockIdx.y + (int)gridDim.y * blockIdx.z);
            w2_slice((const float4*)w2fp, bid, tid);
        }
        return;
    }
    const int n0 = blockIdx.x * BN;
    int off = 0;
    #pragma unroll
    for (int j = 0; j < NEXP; j++) if (j < e) off += g_cnt[j];

    extern __shared__ char dsm[];
    const uint32_t smb = s2u(dsm);

    const int lane = tid & 31, warp = tid >> 5;
    const int wm = warp >> 2, wn = warp & 3;   // 2x4 warp grid

    // tensor: warp tile 64 rows x 24 cols (cols wn*24 .. +24)
    int acc[4][3][4];
    #pragma unroll
    for (int a = 0; a < 4; a++)
        #pragma unroll
        for (int b = 0; b < 3; b++)
            #pragma unroll
            for (int c = 0; c < 4; c++) acc[a][b][c] = 0;
    // dp4a: warp handles rows wm*64..+64 (2 per lane), cols 96 + wn*8 .. +8
    int dacc[2][8];
    #pragma unroll
    for (int a = 0; a < 2; a++)
        #pragma unroll
        for (int b = 0; b < 8; b++) dacc[a][b] = 0;

    const int lr = tid >> 1;            // staged row (0..127)
    const int lcb = (tid & 1) * 32;     // byte offset within 64B k-chunk
    const bool aok = (m0 + lr) < cnt;
    const signed char* Ap;
    if (MODE == 1) {
        int tok = aok ? g_tok[e * TTOK + m0 + lr] : 0;
        Ap = g_xq + (size_t)tok * K + kbase + lcb;
    } else {
        int r = aok ? (off + m0 + lr) : 0;
        Ap = g_hq + (size_t)r * K + kbase + lcb;
    }
    const unsigned aSz = aok ? 16u : 0u;
    const signed char* wsrc = (MODE == 1) ? g_wq1 : g_wq2;
    const signed char* Bp = wsrc + (size_t)e * N * K + (size_t)(n0 + lr) * K + kbase + lcb;

    const uint32_t cpOff = (uint32_t)(lr * LDSS + lcb);
    const uint32_t aLO = (uint32_t)((lane & 15) * LDSS + (lane >> 4) * 16);
    const uint32_t bLO = (uint32_t)(((lane >> 4) * 8 + (lane & 7)) * LDSS + ((lane >> 3) & 1) * 16);
    // dp4a 32-bit smem address offsets (within a stage)
    const uint32_t dA0 = (uint32_t)((wm * 64 + lane) * LDSS);
    const uint32_t dA1 = (uint32_t)((wm * 64 + 32 + lane) * LDSS);
    const uint32_t dB0 = (uint32_t)(BM * LDSS + (96 + wn * 8) * LDSS);

    auto prefetch = [&](int it) {
        int s = it;
        while (s >= 3) s -= 3;
        uint32_t ab = smb + s * STG_STRIDE + cpOff;
        uint32_t bb = ab + BM * LDSS;
        const signed char* as = Ap;
        const signed char* bs = Bp;
        unsigned asz = 0, bsz = 0;
        if (it < NITER) {
            as = Ap + it * BKK;
            bs = Bp + it * BKK;
            asz = aSz;
            bsz = 16;
        }
        asm volatile("cp.async.cg.shared.global [%0], [%1], 16, %2;"
                     :: "r"(ab), "l"(as), "r"(asz) : "memory");
        asm volatile("cp.async.cg.shared.global [%0], [%1], 16, %2;"
                     :: "r"(ab + 16), "l"(as + 16), "r"(asz) : "memory");
        asm volatile("cp.async.cg.shared.global [%0], [%1], 16, %2;"
                     :: "r"(bb), "l"(bs), "r"(bsz) : "memory");
        asm volatile("cp.async.cg.shared.global [%0], [%1], 16, %2;"
                     :: "r"(bb + 16), "l"(bs + 16), "r"(bsz) : "memory");
        asm volatile("cp.async.commit_group;" ::: "memory");
    };

    prefetch(0);
    prefetch(1);
    #pragma unroll 1
    for (int i = 0; i < NITER; i++) {
        prefetch(i + 2);
        asm volatile("cp.async.wait_group 2;" ::: "memory");   // my group-i copies landed
        __syncthreads();                                       // everyone's group-i copies landed
        int s = i;
        while (s >= 3) s -= 3;
        const uint32_t stB = smb + s * STG_STRIDE;
        const uint32_t aB = stB;
        const uint32_t bB = stB + BM * LDSS;

        // tensor part: cols 0..95
        #pragma unroll
        for (int ks = 0; ks < 2; ks++) {
            unsigned af[4][4];
            #pragma unroll
            for (int mi = 0; mi < 4; mi++)
                ldsm4(af[mi][0], af[mi][1], af[mi][2], af[mi][3],
                      aB + (uint32_t)((wm * 64 + mi * 16) * LDSS + ks * 32) + aLO);
            unsigned bf[4][2];
            #pragma unroll
            for (int np = 0; np < 2; np++)
                ldsm4(bf[np * 2][0], bf[np * 2][1], bf[np * 2 + 1][0], bf[np * 2 + 1][1],
                      bB + (uint32_t)((wn * 24 + np * 16) * LDSS + ks * 32) + bLO);
            #pragma unroll
            for (int mi = 0; mi < 4; mi++)
                #pragma unroll
                for (int ni = 0; ni < 3; ni++) mma8(acc[mi][ni], af[mi], bf[ni]);
        }

        // dp4a part: cols 96..127 (fma pipe, concurrent with tensor pipe)
        #pragma unroll 1
        for (int kq = 0; kq < 4; kq++) {
            unsigned a0[4], a1[4];
            lds128(a0[0], a0[1], a0[2], a0[3], stB + dA0 + kq * 16);
            lds128(a1[0], a1[1], a1[2], a1[3], stB + dA1 + kq * 16);
            #pragma unroll
            for (int c = 0; c < 8; c++) {
                unsigned bv[4];
                lds128(bv[0], bv[1], bv[2], bv[3], stB + dB0 + (uint32_t)(c * LDSS) + kq * 16);
                int t0 = dacc[0][c], t1 = dacc[1][c];
                t0 = __dp4a((int)a0[0], (int)bv[0], t0); t1 = __dp4a((int)a1[0], (int)bv[0], t1);
                t0 = __dp4a((int)a0[1], (int)bv[1], t0); t1 = __dp4a((int)a1[1], (int)bv[1], t1);
                t0 = __dp4a((int)a0[2], (int)bv[2], t0); t1 = __dp4a((int)a1[2], (int)bv[2], t1);
                t0 = __dp4a((int)a0[3], (int)bv[3], t0); t1 = __dp4a((int)a1[3], (int)bv[3], t1);
                dacc[0][c] = t0; dacc[1][c] = t1;
            }
        }
        __syncthreads();                                       // release stage i for reuse
    }

    if (MODE == 1) {
        const float m1 = g_mval[2 + e];
        // tensor epilogue: cols 0..95
        #pragma unroll
        for (int mi = 0; mi < 4; mi++) {
            #pragma unroll
            for (int half = 0; half < 2; half++) {
                int rrow = wm * 64 + mi * 16 + (lane >> 2) + half * 8;
                int pos = m0 + rrow;
                if (pos < cnt) {
                    float d = g_deqx[g_tok[e * TTOK + pos]] * m1;
                    float* hrow = g_h + (size_t)(off + pos) * HIDX + n0;
                    #pragma unroll
                    for (int ni = 0; ni < 3; ni++) {
                        int col = wn * 24 + ni * 8 + (lane & 3) * 2;
                        float2 v;
                        v.x = fmaxf(0.f, (float)acc[mi][ni][half * 2 + 0] * d);
                        v.y = fmaxf(0.f, (float)acc[mi][ni][half * 2 + 1] * d);
                        *(float2*)(hrow + col) = v;
                    }
                }
            }
        }
        // dp4a epilogue: cols 96..127
        #pragma unroll
        for (int rr = 0; rr < 2; rr++) {
            int pos = m0 + wm * 64 + rr * 32 + lane;
            if (pos < cnt) {
                float d = g_deqx[g_tok[e * TTOK + pos]] * m1;
                float* hrow = g_h + (size_t)(off + pos) * HIDX + n0 + 96 + wn * 8;
                float4 v0, v1;
                v0.x = fmaxf(0.f, (float)dacc[rr][0] * d);
                v0.y = fmaxf(0.f, (float)dacc[rr][1] * d);
                v0.z = fmaxf(0.f, (float)dacc[rr][2] * d);
                v0.w = fmaxf(0.f, (float)dacc[rr][3] * d);
                v1.x = fmaxf(0.f, (float)dacc[rr][4] * d);
                v1.y = fmaxf(0.f, (float)dacc[rr][5] * d);
                v1.z = fmaxf(0.f, (float)dacc[rr][6] * d);
                v1.w = fmaxf(0.f, (float)dacc[rr][7] * d);
                *(float4*)(hrow) = v0;
                *(float4*)(hrow + 4) = v1;
            }
        }
        // this block's w2 ternarize slice (overlaps with other blocks' MMA work)
        int bid = blockIdx.x + (int)gridDim.x * (blockIdx.y + (int)gridDim.y * blockIdx.z);
        w2_slice((const float4*)w2fp, bid, tid);
    } else {
        int* yp = g_yp + (size_t)ksp * 2 * TTOK * DIMX;
        #pragma unroll
        for (int mi = 0; mi < 4; mi++) {
            #pragma unroll
            for (int half = 0; half < 2; half++) {
                int rrow = wm * 64 + mi * 16 + (lane >> 2) + half * 8;
                int pos = m0 + rrow;
                if (pos < cnt) {
                    int* yrow = yp + (size_t)(off + pos) * DIMX + n0;
                    #pragma unroll
                    for (int ni = 0; ni < 3; ni++) {
                        int col = wn * 24 + ni * 8 + (lane & 3) * 2;
                        int2 v;
                        v.x = acc[mi][ni][half * 2 + 0];
                        v.y = acc[mi][ni][half * 2 + 1];
                        *(int2*)(yrow + col) = v;
                    }
                }
            }
        }
        #pragma unroll
        for (int rr = 0; rr < 2; rr++) {
            int pos = m0 + wm * 64 + rr * 32 + lane;
            if (pos < cnt) {
                int* yrow = yp + (size_t)(off + pos) * DIMX + n0 + 96 + wn * 8;
                int4 v0, v1;
                v0.x = dacc[rr][0]; v0.y = dacc[rr][1]; v0.z = dacc[rr][2]; v0.w = dacc[rr][3];
                v1.x = dacc[rr][4]; v1.y = dacc[rr][5]; v1.z = dacc[rr][6]; v1.w = dacc[rr][7];
                *(int4*)(yrow) = v0;
                *(int4*)(yrow + 4) = v1;
            }
        }
    }
}

// ---------------- 5) hidden quant: one block per packed row ----------------
__global__ void h_quant() {
    size_t row = blockIdx.x;   // 0 .. 2*TTOK-1 (all slots always filled)
    const float4* hp = (const float4*)(g_h + row * HIDX);
    int tid = threadIdx.x;
    float4 r[4];
    float ss = 0.f, am = 0.f;
    #pragma unroll
    for (int j = 0; j < 4; j++) {
        r[j] = hp[tid + 256 * j];
        ss += r[j].x * r[j].x + r[j].y * r[j].y + r[j].z * r[j].z + r[j].w * r[j].w;
        am = fmaxf(am, fmaxf(fmaxf(fabsf(r[j].x), fabsf(r[j].y)), fmaxf(fabsf(r[j].z), fabsf(r[j].w))));
    }
    __shared__ float shs[8], shm[8];
    #pragma unroll
    for (int o = 16; o; o >>= 1) {
        ss += __shfl_xor_sync(0xffffffffu, ss, o);
        am = fmaxf(am, __shfl_xor_sync(0xffffffffu, am, o));
    }
    if ((tid & 31) == 0) { shs[tid >> 5] = ss; shm[tid >> 5] = am; }
    __syncthreads();
    float tss = 0.f, tam = 0.f;
    #pragma unroll
    for (int j = 0; j < 8; j++) { tss += shs[j]; tam = fmaxf(tam, shm[j]); }
    float rs = rsqrtf(tss / (float)HIDX + 1e-6f);
    float a = fmaxf(tam * rs, 1e-5f);
    float sc = 127.0f / a;
    if (tid == 0) g_deqh[row] = a / 127.0f;
    char4* dst = (char4*)(g_hq + row * HIDX);
    #pragma unroll
    for (int j = 0; j < 4; j++) {
        char4 c;
        c.x = qi8(r[j].x * rs * sc); c.y = qi8(r[j].y * rs * sc);
        c.z = qi8(r[j].z * rs * sc); c.w = qi8(r[j].w * rs * sc);
        dst[tid + 256 * j] = c;
    }
}

// ---------------- 7) gated combine (deterministic, atomic-free) ----------------
__global__ void combine(float* __restrict__ out) {
    __shared__ int soff[NEXP];
    int t = blockIdx.x, i = threadIdx.x;
    if (i == 0) {
        int o = 0;
        #pragma unroll
        for (int j = 0; j < NEXP; j++) { soff[j] = o; o += g_cnt[j]; }
    }
    __syncthreads();
    int a0 = g_tpe[t * 2], a1 = g_tpe[t * 2 + 1];
    int e0 = a0 >> 16, e1 = a1 >> 16;
    int row0 = soff[e0] + (a0 & 0xFFFF);
    int row1 = soff[e1] + (a1 & 0xFFFF);
    float d0 = g_deqh[row0] * g_mval[10 + e0] * g_tg[t * 2];
    float d1 = g_deqh[row1] * g_mval[10 + e1] * g_tg[t * 2 + 1];
    size_t r0 = (size_t)row0 * DIMX + (size_t)i * 4;
    size_t r1 = (size_t)row1 * DIMX + (size_t)i * 4;
    int4 s0 = make_int4(0, 0, 0, 0), s1 = s0;
    #pragma unroll
    for (int k = 0; k < KSPL; k++) {
        const int* yp = g_yp + (size_t)k * 2 * TTOK * DIMX;
        int4 p0 = *(const int4*)(yp + r0);
        int4 p1 = *(const int4*)(yp + r1);
        s0.x += p0.x; s0.y += p0.y; s0.z += p0.z; s0.w += p0.w;
        s1.x += p1.x; s1.y += p1.y; s1.z += p1.z; s1.w += p1.w;
    }
    float4 o;
    o.x = (float)s0.x * d0 + (float)s1.x * d1;
    o.y = (float)s0.y * d0 + (float)s1.y * d1;
    o.z = (float)s0.z * d0 + (float)s1.z * d1;
    o.w = (float)s0.w * d0 + (float)s1.w * d1;
    ((float4*)(out + (size_t)t * DIMX))[i] = o;
}

// ---------------- launch ----------------
extern "C" void kernel_launch(void* const* d_in, const int* in_sizes, int n_in,
                              void* d_out, int out_size) {
    const float* x   = (const float*)d_in[0];
    const float* eps = (const float*)d_in[1];
    const float* wr  = (const float*)d_in[2];
    const float* wn  = (const float*)d_in[3];
    const float* w1  = (const float*)d_in[4];
    const float* w2  = (const float*)d_in[5];
    float* out = (float*)d_out;

    cudaFuncSetAttribute(bit_gemm<1>, cudaFuncAttributeMaxDynamicSharedMemorySize, GSMEM);
    cudaFuncSetAttribute(bit_gemm<2>, cudaFuncAttributeMaxDynamicSharedMemorySize, GSMEM);

    stats_partial<<<dim3(128, 18), 256>>>(wr, wn, w1, w2);      // 1
    finalize<<<1, 256>>>(wr, wn);                               // 2
    mega<<<dim3(32768, 1, 2), 256>>>(w1, x, eps);               // 3
    bit_gemm<1><<<dim3(HIDX / BN, TTOK / BM, NEXP), 256, GSMEM>>>(w2);   // 4 <- profiled
    h_quant<<<2 * TTOK, 256>>>();                               // 5
    bit_gemm<2><<<dim3(DIMX / BN, TTOK / BM, NEXP * KSPL), 256, GSMEM>>>(nullptr);  // 6 (4-way K-split)
    combine<<<TTOK, 256>>>(out);                                // 7
}

// round 17
// speedup vs baseline: 1.2476x; 1.0188x over previous
#include <cuda_runtime.h>
#include <cstdint>

#define DIMX 1024
#define NEXP 8
#define HIDX 4096
#define TTOK 4096   // B*S = 2*2048
#define KSPL 4      // gemm2 K-split factor

// ---------------- static scratch (no allocations allowed) ----------------
__device__ signed char g_wq1[(size_t)NEXP * HIDX * DIMX];   // ternary w1
__device__ signed char g_wq2[(size_t)NEXP * DIMX * HIDX];   // ternary w2
__device__ signed char g_wqr[NEXP * DIMX];
__device__ signed char g_wqn[NEXP * DIMX];
__device__ float g_partial[18 * 128];
__device__ float g_mval[18];
__device__ int   g_sdone;            // stats completion counter (reset after use)
__device__ signed char g_xq[(size_t)TTOK * DIMX];
__device__ float g_deqx[TTOK];
__device__ int   g_cnt[NEXP];
__device__ int   g_tok[NEXP * TTOK];
__device__ int   g_tpe[TTOK * 2];    // (expert<<16)|pos per token slot
__device__ float g_tg[TTOK * 2];     // gates per token slot
__device__ float g_h[(size_t)2 * TTOK * HIDX];               // fp32 hidden
__device__ signed char g_hq[(size_t)2 * TTOK * HIDX];        // int8 hidden
__device__ float g_deqh[2 * TTOK];
__device__ int g_yp[(size_t)KSPL * 2 * TTOK * DIMX];         // int32 partials (4 K-quarters)

// ---------------- helpers ----------------
__device__ __forceinline__ signed char terq(float x) {
    float r = rintf(x);
    r = fminf(1.f, fmaxf(-1.f, r));
    return (signed char)(int)r;
}
__device__ __forceinline__ signed char qi8(float x) {
    float r = rintf(x);
    r = fminf(127.f, fmaxf(-128.f, r));
    return (signed char)(int)r;
}
__device__ __forceinline__ uint32_t s2u(const void* p) {
    uint32_t a;
    asm("{ .reg .u64 t; cvta.to.shared.u64 t, %1; cvt.u32.u64 %0, t; }" : "=r"(a) : "l"(p));
    return a;
}
__device__ __forceinline__ void ldsm4(unsigned& r0, unsigned& r1, unsigned& r2, unsigned& r3,
                                      uint32_t a) {
    asm volatile("ldmatrix.sync.aligned.m8n8.x4.shared.b16 {%0,%1,%2,%3}, [%4];"
                 : "=r"(r0), "=r"(r1), "=r"(r2), "=r"(r3) : "r"(a));
}
__device__ __forceinline__ void lds128(unsigned& r0, unsigned& r1, unsigned& r2, unsigned& r3,
                                       uint32_t a) {
    asm volatile("ld.shared.v4.b32 {%0,%1,%2,%3}, [%4];"
                 : "=r"(r0), "=r"(r1), "=r"(r2), "=r"(r3) : "r"(a));
}

// w2 ternarize slice: covers float4 range [sid*1024, sid*1024+1024)
__device__ __forceinline__ void w2_slice(const float4* __restrict__ w2v, int sid, int tid) {
    size_t base = (size_t)sid * 1024;
    #pragma unroll
    for (int j = 0; j < 4; j++) {
        size_t i = base + tid + j * 256;
        int e = (int)(i >> 20);                 // 1048576 float4 per expert
        float sc = 1.0f / g_mval[10 + e];
        float4 v = w2v[i];
        char4 c;
        c.x = terq(v.x * sc); c.y = terq(v.y * sc);
        c.z = terq(v.z * sc); c.w = terq(v.w * sc);
        ((char4*)g_wq2)[i] = c;
    }
}

// ---------------- 1) weight stats + fused finalize (last block) ----------------
__global__ void stats_partial(const float* __restrict__ wr, const float* __restrict__ wn,
                              const float* __restrict__ w1, const float* __restrict__ w2) {
    int slot = blockIdx.y, chunk = blockIdx.x;
    int tid = threadIdx.x;
    bool active = !(slot < 2 && chunk != 0);
    if (active) {
        const float4* p;
        int nvec;
        if (slot < 2) {
            p = (const float4*)(slot ? wn : wr);
            nvec = NEXP * DIMX / 4;
        } else if (slot < 10) {
            p = (const float4*)(w1 + (size_t)(slot - 2) * HIDX * DIMX) + (size_t)chunk * 8192;
            nvec = 8192;
        } else {
            p = (const float4*)(w2 + (size_t)(slot - 10) * DIMX * HIDX) + (size_t)chunk * 8192;
            nvec = 8192;
        }
        float s = 0.f;
        for (int i = tid; i < nvec; i += 256) {
            float4 v = p[i];
            s += fabsf(v.x) + fabsf(v.y) + fabsf(v.z) + fabsf(v.w);
        }
        __shared__ float sh[8];
        #pragma unroll
        for (int o = 16; o; o >>= 1) s += __shfl_xor_sync(0xffffffffu, s, o);
        if ((tid & 31) == 0) sh[tid >> 5] = s;
        __syncthreads();
        if (tid == 0) {
            float t = 0.f;
            #pragma unroll
            for (int j = 0; j < 8; j++) t += sh[j];
            g_partial[slot * 128 + chunk] = t;
        }
    }
    // last-block finalize (all blocks arrive, including inactive ones)
    __threadfence();
    __syncthreads();
    __shared__ int slast;
    if (tid == 0)
        slast = (atomicAdd(&g_sdone, 1) == (int)(gridDim.x * gridDim.y) - 1);
    __syncthreads();
    if (!slast) return;
    __threadfence();   // acquire: all g_partial writes visible
    __shared__ float sm[18];
    if (tid < 18) {
        int nc = (tid < 2) ? 1 : 128;
        float sum = 0.f;
        for (int c = 0; c < nc; c++) sum += g_partial[tid * 128 + c];
        float nelem = (tid < 2) ? (float)(NEXP * DIMX) : (float)((size_t)HIDX * DIMX);
        float m = fmaxf(sum / nelem, 1e-5f);
        g_mval[tid] = m;
        sm[tid] = m;
    }
    if (tid < NEXP) g_cnt[tid] = 0;
    if (tid == 0) g_sdone = 0;   // reset for next graph replay
    __syncthreads();
    float sc0 = 1.0f / sm[0], sc1 = 1.0f / sm[1];
    for (int i = tid; i < NEXP * DIMX; i += 256) {
        g_wqr[i] = terq(wr[i] * sc0);
        g_wqn[i] = terq(wn[i] * sc1);
    }
}

// ---------------- 2) mega: w1 ternarize (z=0) + act-quant+router (z=1) ----------------
__global__ __launch_bounds__(256) void mega(const float* __restrict__ w1,
                                            const float* __restrict__ x,
                                            const float* __restrict__ eps) {
    int z = blockIdx.z;
    int tid = threadIdx.x;
    if (z == 0) {
        size_t i = (size_t)blockIdx.x * 256 + tid;   // float4 index, exactly covers w1
        int e = (int)(i >> 20);
        float sc = 1.0f / g_mval[2 + e];
        float4 v = ((const float4*)w1)[i];
        char4 c;
        c.x = terq(v.x * sc); c.y = terq(v.y * sc); c.z = terq(v.z * sc); c.w = terq(v.w * sc);
        ((char4*)g_wq1)[i] = c;
        return;
    }
    int t = blockIdx.x;
    if (t >= TTOK) return;

    __shared__ float shs[8], shm[8], svals[8], sdq[1];
    __shared__ int sx[256];

    float4 v = ((const float4*)(x + (size_t)t * DIMX))[tid];
    float ss = v.x * v.x + v.y * v.y + v.z * v.z + v.w * v.w;
    float am = fmaxf(fmaxf(fabsf(v.x), fabsf(v.y)), fmaxf(fabsf(v.z), fabsf(v.w)));
    #pragma unroll
    for (int o = 16; o; o >>= 1) {
        ss += __shfl_xor_sync(0xffffffffu, ss, o);
        am = fmaxf(am, __shfl_xor_sync(0xffffffffu, am, o));
    }
    if ((tid & 31) == 0) { shs[tid >> 5] = ss; shm[tid >> 5] = am; }
    __syncthreads();
    float tss = 0.f, tam = 0.f;
    #pragma unroll
    for (int j = 0; j < 8; j++) { tss += shs[j]; tam = fmaxf(tam, shm[j]); }
    float rs = rsqrtf(tss / (float)DIMX + 1e-6f);
    float a = fmaxf(tam * rs, 1e-5f);
    float sc = 127.0f / a;
    if (tid == 0) { g_deqx[t] = a / 127.0f; sdq[0] = a / 127.0f; }
    char4 c;
    c.x = qi8(v.x * rs * sc); c.y = qi8(v.y * rs * sc);
    c.z = qi8(v.z * rs * sc); c.w = qi8(v.w * rs * sc);
    ((char4*)(g_xq + (size_t)t * DIMX))[tid] = c;
    int ci;
    memcpy(&ci, &c, 4);
    sx[tid] = ci;
    __syncthreads();

    // router: warp w handles expert w
    int w = tid >> 5, lane = tid & 31;
    const int* wrp = (const int*)(g_wqr + w * DIMX);
    const int* wnp = (const int*)(g_wqn + w * DIMX);
    int ar = 0, an = 0;
    #pragma unroll
    for (int j = 0; j < 8; j++) {
        int xi = sx[lane + 32 * j];
        ar = __dp4a(xi, wrp[lane + 32 * j], ar);
        an = __dp4a(xi, wnp[lane + 32 * j], an);
    }
    #pragma unroll
    for (int o = 16; o; o >>= 1) {
        ar += __shfl_xor_sync(0xffffffffu, ar, o);
        an += __shfl_xor_sync(0xffffffffu, an, o);
    }
    if (lane == 0) {
        float dq = sdq[0];
        float lg = (float)ar * dq * g_mval[0];
        float nl = (float)an * dq * g_mval[1];
        float sp = fmaxf(nl, 0.f) + log1pf(expf(-fabsf(nl)));
        svals[w] = lg + eps[t * NEXP + w] * sp;
    }
    __syncthreads();
    if (tid == 0) {
        float v0 = -1e30f, v1 = -1e30f;
        int i0 = 0, i1 = 0;
        #pragma unroll
        for (int e = 0; e < NEXP; e++) {
            float vv = svals[e];
            if (vv > v0) { v1 = v0; i1 = i0; v0 = vv; i0 = e; }
            else if (vv > v1) { v1 = vv; i1 = e; }
        }
        float ex = expf(v1 - v0);
        float inv = 1.0f / (1.0f + ex);
        int p0 = atomicAdd(&g_cnt[i0], 1);
        g_tok[i0 * TTOK + p0] = t;
        int p1 = atomicAdd(&g_cnt[i1], 1);
        g_tok[i1 * TTOK + p1] = t;
        g_tpe[t * 2]     = (i0 << 16) | p0;
        g_tpe[t * 2 + 1] = (i1 << 16) | p1;
        g_tg[t * 2]      = inv;
        g_tg[t * 2 + 1]  = ex * inv;
    }
}

// ---------------- 3/5) HYBRID tensor+dp4a int8 grouped GEMM ----------------
// Tile 128x128: cols 0..95 mma.sync (tensor), cols 96..127 dp4a (fma pipe).
// 3-stage cp.async pipeline with ONE barrier per K-iter:
//   wait_group 1 -> own group-i copies done;
//   __syncthreads -> all threads' group-i published AND everyone's compute(i-1)
//   finished (protects stage (i-1)%3 reuse); prefetch(i+2); compute(i).
#define BM 128
#define BN 128
#define BKK 64
#define LDSS 80          // 64 + 16 pad
#define STG_STRIDE (2 * BM * LDSS)   // A stage + B stage = 20480
#define GSMEM (3 * STG_STRIDE)       // 3 stages = 61440 B

__device__ __forceinline__ void mma8(int (&c)[4], const unsigned (&a)[4], const unsigned (&b)[2]) {
    asm volatile(
        "mma.sync.aligned.m16n8k32.row.col.s32.s8.s8.s32 "
        "{%0,%1,%2,%3}, {%4,%5,%6,%7}, {%8,%9}, {%0,%1,%2,%3};\n"
        : "+r"(c[0]), "+r"(c[1]), "+r"(c[2]), "+r"(c[3])
        : "r"(a[0]), "r"(a[1]), "r"(a[2]), "r"(a[3]), "r"(b[0]), "r"(b[1]));
}

template <int MODE>
__global__ __launch_bounds__(256, 3) void bit_gemm(const float* __restrict__ w2fp) {
    constexpr int K = (MODE == 1) ? DIMX : HIDX;
    constexpr int KRUN = (MODE == 1) ? DIMX : HIDX / KSPL;
    constexpr int N = (MODE == 1) ? HIDX : DIMX;
    constexpr int NITER = KRUN / BKK;
    const int e = (MODE == 1) ? blockIdx.z : (blockIdx.z & 7);
    const int ksp = (MODE == 1) ? 0 : (blockIdx.z >> 3);
    const int kbase = ksp * KRUN;
    const int cnt = g_cnt[e];
    const int m0 = blockIdx.y * BM;
    const int tid = threadIdx.x;
    if (m0 >= cnt) {
        if (MODE == 1) {
            int bid = blockIdx.x + (int)gridDim.x * (blockIdx.y + (int)gridDim.y * blockIdx.z);
            w2_slice((const float4*)w2fp, bid, tid);
        }
        return;
    }
    const int n0 = blockIdx.x * BN;
    int off = 0;
    #pragma unroll
    for (int j = 0; j < NEXP; j++) if (j < e) off += g_cnt[j];

    extern __shared__ char dsm[];
    const uint32_t smb = s2u(dsm);

    const int lane = tid & 31, warp = tid >> 5;
    const int wm = warp >> 2, wn = warp & 3;

    int acc[4][3][4];
    #pragma unroll
    for (int a = 0; a < 4; a++)
        #pragma unroll
        for (int b = 0; b < 3; b++)
            #pragma unroll
            for (int c = 0; c < 4; c++) acc[a][b][c] = 0;
    int dacc[2][8];
    #pragma unroll
    for (int a = 0; a < 2; a++)
        #pragma unroll
        for (int b = 0; b < 8; b++) dacc[a][b] = 0;

    const int lr = tid >> 1;
    const int lcb = (tid & 1) * 32;
    const bool aok = (m0 + lr) < cnt;
    const signed char* Ap;
    if (MODE == 1) {
        int tok = aok ? g_tok[e * TTOK + m0 + lr] : 0;
        Ap = g_xq + (size_t)tok * K + kbase + lcb;
    } else {
        int r = aok ? (off + m0 + lr) : 0;
        Ap = g_hq + (size_t)r * K + kbase + lcb;
    }
    const unsigned aSz = aok ? 16u : 0u;
    const signed char* wsrc = (MODE == 1) ? g_wq1 : g_wq2;
    const signed char* Bp = wsrc + (size_t)e * N * K + (size_t)(n0 + lr) * K + kbase + lcb;

    const uint32_t cpOff = (uint32_t)(lr * LDSS + lcb);
    const uint32_t aLO = (uint32_t)((lane & 15) * LDSS + (lane >> 4) * 16);
    const uint32_t bLO = (uint32_t)(((lane >> 4) * 8 + (lane & 7)) * LDSS + ((lane >> 3) & 1) * 16);
    const uint32_t dA0 = (uint32_t)((wm * 64 + lane) * LDSS);
    const uint32_t dA1 = (uint32_t)((wm * 64 + 32 + lane) * LDSS);
    const uint32_t dB0 = (uint32_t)(BM * LDSS + (96 + wn * 8) * LDSS);

    auto prefetch = [&](int it) {
        int s = it;
        while (s >= 3) s -= 3;
        uint32_t ab = smb + s * STG_STRIDE + cpOff;
        uint32_t bb = ab + BM * LDSS;
        const signed char* as = Ap;
        const signed char* bs = Bp;
        unsigned asz = 0, bsz = 0;
        if (it < NITER) {
            as = Ap + it * BKK;
            bs = Bp + it * BKK;
            asz = aSz;
            bsz = 16;
        }
        asm volatile("cp.async.cg.shared.global [%0], [%1], 16, %2;"
                     :: "r"(ab), "l"(as), "r"(asz) : "memory");
        asm volatile("cp.async.cg.shared.global [%0], [%1], 16, %2;"
                     :: "r"(ab + 16), "l"(as + 16), "r"(asz) : "memory");
        asm volatile("cp.async.cg.shared.global [%0], [%1], 16, %2;"
                     :: "r"(bb), "l"(bs), "r"(bsz) : "memory");
        asm volatile("cp.async.cg.shared.global [%0], [%1], 16, %2;"
                     :: "r"(bb + 16), "l"(bs + 16), "r"(bsz) : "memory");
        asm volatile("cp.async.commit_group;" ::: "memory");
    };

    prefetch(0);
    prefetch(1);
    #pragma unroll 1
    for (int i = 0; i < NITER; i++) {
        asm volatile("cp.async.wait_group 1;" ::: "memory");  // own group-i done
        __syncthreads();   // all group-i published; all compute(i-1) done
        prefetch(i + 2);   // overwrites stage (i-1)%3 -- safe after barrier
        int s = i;
        while (s >= 3) s -= 3;
        const uint32_t stB = smb + s * STG_STRIDE;
        const uint32_t aB = stB;
        const uint32_t bB = stB + BM * LDSS;

        #pragma unroll
        for (int ks = 0; ks < 2; ks++) {
            unsigned af[4][4];
            #pragma unroll
            for (int mi = 0; mi < 4; mi++)
                ldsm4(af[mi][0], af[mi][1], af[mi][2], af[mi][3],
                      aB + (uint32_t)((wm * 64 + mi * 16) * LDSS + ks * 32) + aLO);
            unsigned bf[4][2];
            #pragma unroll
            for (int np = 0; np < 2; np++)
                ldsm4(bf[np * 2][0], bf[np * 2][1], bf[np * 2 + 1][0], bf[np * 2 + 1][1],
                      bB + (uint32_t)((wn * 24 + np * 16) * LDSS + ks * 32) + bLO);
            #pragma unroll
            for (int mi = 0; mi < 4; mi++)
                #pragma unroll
                for (int ni = 0; ni < 3; ni++) mma8(acc[mi][ni], af[mi], bf[ni]);
        }

        #pragma unroll 1
        for (int kq = 0; kq < 4; kq++) {
            unsigned a0[4], a1[4];
            lds128(a0[0], a0[1], a0[2], a0[3], stB + dA0 + kq * 16);
            lds128(a1[0], a1[1], a1[2], a1[3], stB + dA1 + kq * 16);
            #pragma unroll
            for (int c = 0; c < 8; c++) {
                unsigned bv[4];
                lds128(bv[0], bv[1], bv[2], bv[3], stB + dB0 + (uint32_t)(c * LDSS) + kq * 16);
                int t0 = dacc[0][c], t1 = dacc[1][c];
                t0 = __dp4a((int)a0[0], (int)bv[0], t0); t1 = __dp4a((int)a1[0], (int)bv[0], t1);
                t0 = __dp4a((int)a0[1], (int)bv[1], t0); t1 = __dp4a((int)a1[1], (int)bv[1], t1);
                t0 = __dp4a((int)a0[2], (int)bv[2], t0); t1 = __dp4a((int)a1[2], (int)bv[2], t1);
                t0 = __dp4a((int)a0[3], (int)bv[3], t0); t1 = __dp4a((int)a1[3], (int)bv[3], t1);
                dacc[0][c] = t0; dacc[1][c] = t1;
            }
        }
    }

    if (MODE == 1) {
        const float m1 = g_mval[2 + e];
        #pragma unroll
        for (int mi = 0; mi < 4; mi++) {
            #pragma unroll
            for (int half = 0; half < 2; half++) {
                int rrow = wm * 64 + mi * 16 + (lane >> 2) + half * 8;
                int pos = m0 + rrow;
                if (pos < cnt) {
                    float d = g_deqx[g_tok[e * TTOK + pos]] * m1;
                    float* hrow = g_h + (size_t)(off + pos) * HIDX + n0;
                    #pragma unroll
                    for (int ni = 0; ni < 3; ni++) {
                        int col = wn * 24 + ni * 8 + (lane & 3) * 2;
                        float2 v;
                        v.x = fmaxf(0.f, (float)acc[mi][ni][half * 2 + 0] * d);
                        v.y = fmaxf(0.f, (float)acc[mi][ni][half * 2 + 1] * d);
                        *(float2*)(hrow + col) = v;
                    }
                }
            }
        }
        #pragma unroll
        for (int rr = 0; rr < 2; rr++) {
            int pos = m0 + wm * 64 + rr * 32 + lane;
            if (pos < cnt) {
                float d = g_deqx[g_tok[e * TTOK + pos]] * m1;
                float* hrow = g_h + (size_t)(off + pos) * HIDX + n0 + 96 + wn * 8;
                float4 v0, v1;
                v0.x = fmaxf(0.f, (float)dacc[rr][0] * d);
                v0.y = fmaxf(0.f, (float)dacc[rr][1] * d);
                v0.z = fmaxf(0.f, (float)dacc[rr][2] * d);
                v0.w = fmaxf(0.f, (float)dacc[rr][3] * d);
                v1.x = fmaxf(0.f, (float)dacc[rr][4] * d);
                v1.y = fmaxf(0.f, (float)dacc[rr][5] * d);
                v1.z = fmaxf(0.f, (float)dacc[rr][6] * d);
                v1.w = fmaxf(0.f, (float)dacc[rr][7] * d);
                *(float4*)(hrow) = v0;
                *(float4*)(hrow + 4) = v1;
            }
        }
        int bid = blockIdx.x + (int)gridDim.x * (blockIdx.y + (int)gridDim.y * blockIdx.z);
        w2_slice((const float4*)w2fp, bid, tid);
    } else {
        int* yp = g_yp + (size_t)ksp * 2 * TTOK * DIMX;
        #pragma unroll
        for (int mi = 0; mi < 4; mi++) {
            #pragma unroll
            for (int half = 0; half < 2; half++) {
                int rrow = wm * 64 + mi * 16 + (lane >> 2) + half * 8;
                int pos = m0 + rrow;
                if (pos < cnt) {
                    int* yrow = yp + (size_t)(off + pos) * DIMX + n0;
                    #pragma unroll
                    for (int ni = 0; ni < 3; ni++) {
                        int col = wn * 24 + ni * 8 + (lane & 3) * 2;
                        int2 v;
                        v.x = acc[mi][ni][half * 2 + 0];
                        v.y = acc[mi][ni][half * 2 + 1];
                        *(int2*)(yrow + col) = v;
                    }
                }
            }
        }
        #pragma unroll
        for (int rr = 0; rr < 2; rr++) {
            int pos = m0 + wm * 64 + rr * 32 + lane;
            if (pos < cnt) {
                int* yrow = yp + (size_t)(off + pos) * DIMX + n0 + 96 + wn * 8;
                int4 v0, v1;
                v0.x = dacc[rr][0]; v0.y = dacc[rr][1]; v0.z = dacc[rr][2]; v0.w = dacc[rr][3];
                v1.x = dacc[rr][4]; v1.y = dacc[rr][5]; v1.z = dacc[rr][6]; v1.w = dacc[rr][7];
                *(int4*)(yrow) = v0;
                *(int4*)(yrow + 4) = v1;
            }
        }
    }
}

// ---------------- 4) hidden quant: one block per packed row ----------------
__global__ void h_quant() {
    size_t row = blockIdx.x;
    const float4* hp = (const float4*)(g_h + row * HIDX);
    int tid = threadIdx.x;
    float4 r[4];
    float ss = 0.f, am = 0.f;
    #pragma unroll
    for (int j = 0; j < 4; j++) {
        r[j] = hp[tid + 256 * j];
        ss += r[j].x * r[j].x + r[j].y * r[j].y + r[j].z * r[j].z + r[j].w * r[j].w;
        am = fmaxf(am, fmaxf(fmaxf(fabsf(r[j].x), fabsf(r[j].y)), fmaxf(fabsf(r[j].z), fabsf(r[j].w))));
    }
    __shared__ float shs[8], shm[8];
    #pragma unroll
    for (int o = 16; o; o >>= 1) {
        ss += __shfl_xor_sync(0xffffffffu, ss, o);
        am = fmaxf(am, __shfl_xor_sync(0xffffffffu, am, o));
    }
    if ((tid & 31) == 0) { shs[tid >> 5] = ss; shm[tid >> 5] = am; }
    __syncthreads();
    float tss = 0.f, tam = 0.f;
    #pragma unroll
    for (int j = 0; j < 8; j++) { tss += shs[j]; tam = fmaxf(tam, shm[j]); }
    float rs = rsqrtf(tss / (float)HIDX + 1e-6f);
    float a = fmaxf(tam * rs, 1e-5f);
    float sc = 127.0f / a;
    if (tid == 0) g_deqh[row] = a / 127.0f;
    char4* dst = (char4*)(g_hq + row * HIDX);
    #pragma unroll
    for (int j = 0; j < 4; j++) {
        char4 c;
        c.x = qi8(r[j].x * rs * sc); c.y = qi8(r[j].y * rs * sc);
        c.z = qi8(r[j].z * rs * sc); c.w = qi8(r[j].w * rs * sc);
        dst[tid + 256 * j] = c;
    }
}

// ---------------- 6) gated combine (deterministic, atomic-free) ----------------
__global__ void combine(float* __restrict__ out) {
    __shared__ int soff[NEXP];
    int t = blockIdx.x, i = threadIdx.x;
    if (i == 0) {
        int o = 0;
        #pragma unroll
        for (int j = 0; j < NEXP; j++) { soff[j] = o; o += g_cnt[j]; }
    }
    __syncthreads();
    int a0 = g_tpe[t * 2], a1 = g_tpe[t * 2 + 1];
    int e0 = a0 >> 16, e1 = a1 >> 16;
    int row0 = soff[e0] + (a0 & 0xFFFF);
    int row1 = soff[e1] + (a1 & 0xFFFF);
    float d0 = g_deqh[row0] * g_mval[10 + e0] * g_tg[t * 2];
    float d1 = g_deqh[row1] * g_mval[10 + e1] * g_tg[t * 2 + 1];
    size_t r0 = (size_t)row0 * DIMX + (size_t)i * 4;
    size_t r1 = (size_t)row1 * DIMX + (size_t)i * 4;
    int4 s0 = make_int4(0, 0, 0, 0), s1 = s0;
    #pragma unroll
    for (int k = 0; k < KSPL; k++) {
        const int* yp = g_yp + (size_t)k * 2 * TTOK * DIMX;
        int4 p0 = *(const int4*)(yp + r0);
        int4 p1 = *(const int4*)(yp + r1);
        s0.x += p0.x; s0.y += p0.y; s0.z += p0.z; s0.w += p0.w;
        s1.x += p1.x; s1.y += p1.y; s1.z += p1.z; s1.w += p1.w;
    }
    float4 o;
    o.x = (float)s0.x * d0 + (float)s1.x * d1;
    o.y = (float)s0.y * d0 + (float)s1.y * d1;
    o.z = (float)s0.z * d0 + (float)s1.z * d1;
    o.w = (float)s0.w * d0 + (float)s1.w * d1;
    ((float4*)(out + (size_t)t * DIMX))[i] = o;
}

// ---------------- launch ----------------
extern "C" void kernel_launch(void* const* d_in, const int* in_sizes, int n_in,
                              void* d_out, int out_size) {
    const float* x   = (const float*)d_in[0];
    const float* eps = (const float*)d_in[1];
    const float* wr  = (const float*)d_in[2];
    const float* wn  = (const float*)d_in[3];
    const float* w1  = (const float*)d_in[4];
    const float* w2  = (const float*)d_in[5];
    float* out = (float*)d_out;

    cudaFuncSetAttribute(bit_gemm<1>, cudaFuncAttributeMaxDynamicSharedMemorySize, GSMEM);
    cudaFuncSetAttribute(bit_gemm<2>, cudaFuncAttributeMaxDynamicSharedMemorySize, GSMEM);

    stats_partial<<<dim3(128, 18), 256>>>(wr, wn, w1, w2);      // 1 (finalize fused)
    mega<<<dim3(32768, 1, 2), 256>>>(w1, x, eps);               // 2
    bit_gemm<1><<<dim3(HIDX / BN, TTOK / BM, NEXP), 256, GSMEM>>>(w2);   // 3
    h_quant<<<2 * TTOK, 256>>>();                               // 4 <- profiled slot
    bit_gemm<2><<<dim3(DIMX / BN, TTOK / BM, NEXP * KSPL), 256, GSMEM>>>(nullptr);  // 5
    combine<<<TTOK, 256>>>(out);                                // 6
}